// round 13
// baseline (speedup 1.0000x reference)
#include <cuda_runtime.h>
#include <cuda_fp16.h>
#include <cstdint>
#include <math.h>

// ---------------- problem constants ----------------
#define T_TOK   4096
#define DIM     2048
#define NH      16
#define NKV     4
#define HD      128
// 1/sqrt(128) * log2(e)  — absorbed into Q at the GEMM epilogue
#define QSCALE_LOG2E 0.12751744f

// ---------------- HMMA GEMM constants ----------------
#define BM 128
#define BN 128
#define BK 32
#define GPAD 40
#define GBH_OFF (128 * GPAD)
#define GSTG_H  (GBH_OFF + 2 * 128 * GPAD)  // 15360 halves/stage
#define STAGE_B (GSTG_H * 2)
#define NSTAGE 3
#define GEMM_SMEM (NSTAGE * STAGE_B)

// ---------------- flash constants ----------------
#define FQB  128
#define FKB  64
#define KROW 136
#define VROW 72
#define QL_H   (FQB * KROW)
#define STG0_H (2 * FQB * KROW)
#define VH_H   (FKB * KROW)
#define STG_H  (VH_H + HD * VROW)
#define FLASH_SMEM ((STG0_H + 2 * STG_H) * 2)

extern __shared__ __align__(16) char dyn_smem[];

// -------- scratch (device globals) --------
__device__ float  g_V[T_TOK * NKV * HD];
__device__ __half g_xh[T_TOK * DIM];
__device__ __half g_ah[T_TOK * DIM];
__device__ __half g_wqkvh[3072 * DIM], g_wqkvl[3072 * DIM];
__device__ __half g_woh[DIM * DIM];
__device__ __half g_qh[T_TOK * NH * HD],  g_ql[T_TOK * NH * HD];
__device__ __half g_kh[T_TOK * NKV * HD];
__device__ __half g_vth[NKV * HD * T_TOK];

// ---------------- helpers ----------------
__device__ __forceinline__ uint32_t smem_u32(const void* p) {
    uint32_t a;
    asm("{ .reg .u64 t; cvta.to.shared.u64 t, %1; cvt.u32.u64 %0, t; }" : "=r"(a) : "l"(p));
    return a;
}
__device__ __forceinline__ void cp16(void* dst, const void* src) {
    uint32_t d;
    asm("{ .reg .u64 t; cvta.to.shared.u64 t, %1; cvt.u32.u64 %0, t; }" : "=r"(d) : "l"(dst));
    asm volatile("cp.async.cg.shared.global [%0], [%1], 16;" :: "r"(d), "l"(src));
}
__device__ __forceinline__ void mma16816(float* c, const uint32_t* a, const uint32_t* b) {
    asm volatile(
        "mma.sync.aligned.m16n8k16.row.col.f32.f16.f16.f32 "
        "{%0,%1,%2,%3}, {%4,%5,%6,%7}, {%8,%9}, {%0,%1,%2,%3};"
        : "+f"(c[0]), "+f"(c[1]), "+f"(c[2]), "+f"(c[3])
        : "r"(a[0]), "r"(a[1]), "r"(a[2]), "r"(a[3]), "r"(b[0]), "r"(b[1]));
}
#define LDSM4(R, a) \
    asm volatile("ldmatrix.sync.aligned.m8n8.x4.shared.b16 {%0,%1,%2,%3}, [%4];" \
        : "=r"((R)[0]), "=r"((R)[1]), "=r"((R)[2]), "=r"((R)[3]) : "r"(a))
__device__ __forceinline__ uint32_t ex2_f16x2(__half2 x) {
    uint32_t r;
    asm("ex2.approx.f16x2 %0, %1;" : "=r"(r) : "r"(*(uint32_t*)&x));
    return r;
}
__device__ __forceinline__ float ex2_f32(float x) {
    float r;
    asm("ex2.approx.f32 %0, %1;" : "=f"(r) : "f"(x));
    return r;
}

// ---------------- pack x: fp32 -> hi fp16 ----------------
__global__ void __launch_bounds__(256) pack_hi(const float* __restrict__ in,
                                               __half* __restrict__ oh, int n4) {
    int i = blockIdx.x * blockDim.x + threadIdx.x;
    if (i >= n4) return;
    float4 v = ((const float4*)in)[i];
    ((__half2*)oh)[i * 2 + 0] = __floats2half2_rn(v.x, v.y);
    ((__half2*)oh)[i * 2 + 1] = __floats2half2_rn(v.z, v.w);
}

// ---------------- fused weight transpose+split ----------------
__global__ void __launch_bounds__(256) pack_w_all(const float* __restrict__ wq,
                                                  const float* __restrict__ wk,
                                                  const float* __restrict__ wv,
                                                  const float* __restrict__ wo,
                                                  __half* __restrict__ qkvh,
                                                  __half* __restrict__ qkvl,
                                                  __half* __restrict__ woh) {
    __shared__ float t[32][33];
    int k0 = blockIdx.x * 32;
    int by = blockIdx.y;
    const float* w; __half *oh, *ol;
    int Nsrc, nbase, n0;
    if (by < 64)       { w = wq; Nsrc = 2048; nbase = 0;    n0 = by * 32;        oh = qkvh; ol = qkvl; }
    else if (by < 80)  { w = wk; Nsrc = 512;  nbase = 2048; n0 = (by - 64) * 32; oh = qkvh; ol = qkvl; }
    else if (by < 96)  { w = wv; Nsrc = 512;  nbase = 2560; n0 = (by - 80) * 32; oh = qkvh; ol = qkvl; }
    else               { w = wo; Nsrc = 2048; nbase = 0;    n0 = (by - 96) * 32; oh = woh;  ol = nullptr; }
    int tid = threadIdx.x;
    int cc = tid & 31, rr = tid >> 5;
#pragma unroll
    for (int i = 0; i < 4; i++) {
        int row = rr + i * 8;
        t[row][cc] = w[(size_t)(k0 + row) * Nsrc + n0 + cc];
    }
    __syncthreads();
#pragma unroll
    for (int i = 0; i < 4; i++) {
        int n = rr + i * 8;
        float v = t[cc][n];
        __half h = __float2half_rn(v);
        size_t o = (size_t)(nbase + n0 + n) * DIM + k0 + cc;
        oh[o] = h;
        if (ol) ol[o] = __float2half_rn(v - __half2float(h));
    }
}

// ---------------- HMMA GEMM, templated epilogue ----------------
// MODE 0: QKV — Q-tiles 2-product, K/V-tiles 1-product; RoPE epilogue -> qh/ql/kh fp16 + V fp32
// MODE 1: WO  — 1-product, plain fp32 output
template<int MODE>
__global__ void __launch_bounds__(256, 2) gemm_hmma(const __half* __restrict__ Ah,
                                                    const __half* __restrict__ Bh,
                                                    const __half* __restrict__ Bl,
                                                    __half* __restrict__ qh,
                                                    __half* __restrict__ ql,
                                                    __half* __restrict__ kh,
                                                    float* __restrict__ Vout,
                                                    const float* __restrict__ fc,
                                                    const float* __restrict__ fs) {
    __half* sm = (__half*)dyn_smem;
    const int tid = threadIdx.x;
    const int wid = tid >> 5, lane = tid & 31;
    const int wm = (wid & 1) * 64, wn = (wid >> 1) * 32;
    const int lg = lane >> 2, lt = lane & 3;

    const size_t arow0 = (size_t)blockIdx.y * BM;
    const size_t brow0 = (size_t)blockIdx.x * BN;
    const bool use_lo = (MODE == 0) && ((int)(blockIdx.x * BN) < 2048);
    constexpr int NCOPY = (MODE == 0) ? 6 : 4;

    float acc[4][4][4];
#pragma unroll
    for (int mf = 0; mf < 4; mf++)
#pragma unroll
        for (int nf = 0; nf < 4; nf++)
#pragma unroll
            for (int q = 0; q < 4; q++) acc[mf][nf][q] = 0.f;

    const int NKT = DIM / BK;

#define G_ISSUE(KT, ST) do {                                                     \
    __half* _sb = sm + (ST) * GSTG_H;                                            \
    int _k0 = (KT) * BK;                                                         \
    _Pragma("unroll")                                                            \
    for (int _i = 0; _i < NCOPY; _i++) {                                         \
        int _idx = tid + _i * 256;                                               \
        if (_idx < 512) {                                                        \
            int _row = _idx >> 2, _ch = _idx & 3;                                \
            cp16(_sb + _row * GPAD + _ch * 8,                                    \
                 Ah + (arow0 + _row) * DIM + _k0 + _ch * 8);                     \
        } else {                                                                 \
            int _j = _idx - 512;                                                 \
            int _sp = _j >> 9, _rem = _j & 511;                                  \
            if (_sp == 0 || use_lo) {                                            \
                int _row = _rem >> 2, _ch = _rem & 3;                            \
                const __half* _src = (_sp ? Bl : Bh)                             \
                    + (brow0 + _row) * DIM + _k0 + _ch * 8;                      \
                cp16(_sb + GBH_OFF + _sp * (128 * GPAD) + _row * GPAD + _ch * 8, _src); \
            }                                                                    \
        }                                                                        \
    }                                                                            \
    asm volatile("cp.async.commit_group;" ::: "memory");                         \
} while (0)

    G_ISSUE(0, 0);
    G_ISSUE(1, 1);

    const uint32_t smb = smem_u32(sm);
    const int a_row = (lane & 15);
    const int a_ch  = (lane >> 4) * 8;
    const int b_row = ((lane >> 4) & 1) * 8 + (lane & 7);
    const int b_ch  = ((lane >> 3) & 1) * 8;

    for (int kt = 0; kt < NKT; kt++) {
        int st = kt % NSTAGE;
        if (kt + 1 < NKT) asm volatile("cp.async.wait_group 1;" ::: "memory");
        else              asm volatile("cp.async.wait_group 0;" ::: "memory");
        __syncthreads();
        if (kt + 2 < NKT) G_ISSUE(kt + 2, (kt + 2) % NSTAGE);

        const uint32_t sb = smb + st * STAGE_B;

#pragma unroll
        for (int ks = 0; ks < 2; ks++) {
            uint32_t ah[4][4];
#pragma unroll
            for (int mf = 0; mf < 4; mf++) {
                uint32_t ao = sb + ((wm + mf * 16 + a_row) * GPAD + ks * 16 + a_ch) * 2;
                LDSM4(ah[mf], ao);
            }
#pragma unroll
            for (int np = 0; np < 2; np++) {
                uint32_t bo = sb + (GBH_OFF + (wn + np * 16 + b_row) * GPAD + ks * 16 + b_ch) * 2;
                uint32_t b4h[4], b4l[4];
                LDSM4(b4h, bo);
                if (use_lo) LDSM4(b4l, bo + (128 * GPAD) * 2);
#pragma unroll
                for (int half = 0; half < 2; half++) {
                    int nf = np * 2 + half;
#pragma unroll
                    for (int mf = 0; mf < 4; mf++) {
                        mma16816(acc[mf][nf], ah[mf], b4h + half * 2);
                        if (use_lo) mma16816(acc[mf][nf], ah[mf], b4l + half * 2);
                    }
                }
            }
        }
    }

    // ---- epilogue ----
    const int nblock = blockIdx.x * BN;
#pragma unroll
    for (int mf = 0; mf < 4; mf++) {
        size_t row0 = arow0 + wm + mf * 16 + lg;
        size_t row1 = row0 + 8;
#pragma unroll
        for (int nf = 0; nf < 4; nf++) {
            int ncol = nblock + wn + nf * 8 + lt * 2;
            if (MODE == 1) {
                *(float2*)(Vout + row0 * 2048 + ncol) = make_float2(acc[mf][nf][0], acc[mf][nf][1]);
                *(float2*)(Vout + row1 * 2048 + ncol) = make_float2(acc[mf][nf][2], acc[mf][nf][3]);
            } else if (ncol < 2048) {
                // Q with RoPE, pre-scaled by scale*log2(e) -> qh/ql fp16
                int pair = (ncol & 127) >> 1;
                float c0 = fc[row0 * 64 + pair], s0 = fs[row0 * 64 + pair];
                float c1 = fc[row1 * 64 + pair], s1 = fs[row1 * 64 + pair];
                float q00 = (acc[mf][nf][0] * c0 - acc[mf][nf][1] * s0) * QSCALE_LOG2E;
                float q01 = (acc[mf][nf][0] * s0 + acc[mf][nf][1] * c0) * QSCALE_LOG2E;
                float q10 = (acc[mf][nf][2] * c1 - acc[mf][nf][3] * s1) * QSCALE_LOG2E;
                float q11 = (acc[mf][nf][2] * s1 + acc[mf][nf][3] * c1) * QSCALE_LOG2E;
                __half2 h0 = __floats2half2_rn(q00, q01);
                __half2 h1 = __floats2half2_rn(q10, q11);
                float2 f0 = __half22float2(h0), f1 = __half22float2(h1);
                *(__half2*)(qh + row0 * 2048 + ncol) = h0;
                *(__half2*)(qh + row1 * 2048 + ncol) = h1;
                *(__half2*)(ql + row0 * 2048 + ncol) = __floats2half2_rn(q00 - f0.x, q01 - f0.y);
                *(__half2*)(ql + row1 * 2048 + ncol) = __floats2half2_rn(q10 - f1.x, q11 - f1.y);
            } else if (ncol < 2560) {
                int kcol = ncol - 2048;
                int pair = (kcol & 127) >> 1;
                float c0 = fc[row0 * 64 + pair], s0 = fs[row0 * 64 + pair];
                float c1 = fc[row1 * 64 + pair], s1 = fs[row1 * 64 + pair];
                float k00 = acc[mf][nf][0] * c0 - acc[mf][nf][1] * s0;
                float k01 = acc[mf][nf][0] * s0 + acc[mf][nf][1] * c0;
                float k10 = acc[mf][nf][2] * c1 - acc[mf][nf][3] * s1;
                float k11 = acc[mf][nf][2] * s1 + acc[mf][nf][3] * c1;
                *(__half2*)(kh + row0 * 512 + kcol) = __floats2half2_rn(k00, k01);
                *(__half2*)(kh + row1 * 512 + kcol) = __floats2half2_rn(k10, k11);
            } else {
                int vcol = ncol - 2560;
                *(float2*)(Vout + row0 * 512 + vcol) = make_float2(acc[mf][nf][0], acc[mf][nf][1]);
                *(float2*)(Vout + row1 * 512 + vcol) = make_float2(acc[mf][nf][2], acc[mf][nf][3]);
            }
        }
    }
}

// ---------------- V transpose (hi only) ----------------
__global__ void __launch_bounds__(256) transpose_v(const float* __restrict__ V,
                                                   __half* __restrict__ vth)
{
    __shared__ float t[32][33];
    int kv = blockIdx.z, t0 = blockIdx.x * 32, d0 = blockIdx.y * 32;
    int cc = threadIdx.x & 31, rr = threadIdx.x >> 5;
#pragma unroll
    for (int i = 0; i < 4; i++) {
        int tok = rr + i * 8;
        t[tok][cc] = V[((size_t)(t0 + tok) * NKV + kv) * HD + d0 + cc];
    }
    __syncthreads();
#pragma unroll
    for (int i = 0; i < 4; i++) {
        int dd = rr + i * 8;
        size_t o = ((size_t)kv * HD + d0 + dd) * T_TOK + t0 + cc;
        vth[o] = __float2half_rn(t[cc][dd]);
    }
}

// ---------------- flash attention: base-2 scores, f16x2 exp ----------------
__global__ void __launch_bounds__(256) flash_hmma(
    const __half* __restrict__ qh, const __half* __restrict__ ql,
    const __half* __restrict__ kh, const __half* __restrict__ vth,
    const int* __restrict__ sid, __half* __restrict__ Aout)
{
    __half* S = (__half*)dyn_smem;
    const int tid = threadIdx.x, wid = tid >> 5, lane = tid & 31;
    const int lg = lane >> 2, lt = lane & 3;
    const int h = blockIdx.y, kv = h >> 2;
    const int q0 = (gridDim.x - 1 - blockIdx.x) * FQB;

#pragma unroll
    for (int i = 0; i < 16; i++) {
        int id = tid + i * 256;
        int sp = id >> 11, rem = id & 2047;
        int row = rem >> 4, ch = rem & 15;
        const __half* src = (sp ? ql : qh) + ((size_t)(q0 + row) * NH + h) * HD + ch * 8;
        cp16(S + sp * QL_H + row * KROW + ch * 8, src);
    }
    asm volatile("cp.async.commit_group;" ::: "memory");

#define F_ISSUE(KB, ST) do {                                                          \
    __half* _s = S + STG0_H + (ST) * STG_H;                                           \
    int _t0 = (KB) * FKB;                                                             \
    _Pragma("unroll")                                                                 \
    for (int _i = 0; _i < 4; _i++) {                                                  \
        int _id = tid + _i * 256;                                                     \
        int _row = _id >> 4, _ch = _id & 15;                                          \
        cp16(_s + _row * KROW + _ch * 8,                                              \
             kh + ((size_t)(_t0 + _row) * NKV + kv) * HD + _ch * 8);                  \
    }                                                                                 \
    _Pragma("unroll")                                                                 \
    for (int _i = 0; _i < 4; _i++) {                                                  \
        int _id = tid + _i * 256;                                                     \
        int _row = _id >> 3, _ch = _id & 7;                                           \
        cp16(_s + VH_H + _row * VROW + _ch * 8,                                       \
             vth + ((size_t)kv * HD + _row) * T_TOK + _t0 + _ch * 8);                 \
    }                                                                                 \
    asm volatile("cp.async.commit_group;" ::: "memory");                              \
} while (0)

    const int qi0 = q0 + wid * 16 + lg, qi1 = qi0 + 8;
    const int sqr0 = sid[qi0], sqr1 = sid[qi1];
    const int sq_first = sid[q0];
    const int sq_last  = sid[q0 + FQB - 1];
    const int kbe = q0 / FKB + 1;
    int kb0 = kbe;
    for (int kb = 0; kb <= kbe; kb++) {
        if (sid[kb * FKB + FKB - 1] >= sq_first) { kb0 = kb; break; }
    }

    F_ISSUE(kb0, 0);
    if (kb0 + 1 <= kbe) F_ISSUE(kb0 + 1, 1);

    float o[16][4];
#pragma unroll
    for (int i = 0; i < 16; i++)
#pragma unroll
        for (int j = 0; j < 4; j++) o[i][j] = 0.f;
    float m0 = -1.0e30f, l0 = 0.f, m1 = -1.0e30f, l1 = 0.f;

    const uint32_t Sb = smem_u32(S);
    const uint32_t q_off = Sb + (((wid * 16 + (lane & 15)) * KROW) + (lane >> 4) * 8) * 2;
    const int k_row = ((lane >> 4) & 1) * 8 + (lane & 7);
    const int k_ch  = ((lane >> 3) & 1) * 8;
    const int v_row = lane & 7;
    const int v_ch  = (lane >> 3) * 8;

    for (int kb = kb0; kb <= kbe; kb++) {
        int st = (kb - kb0) & 1;
        if (kb + 1 <= kbe) asm volatile("cp.async.wait_group 1;" ::: "memory");
        else               asm volatile("cp.async.wait_group 0;" ::: "memory");
        __syncthreads();

        const uint32_t Kb = Sb + (STG0_H + st * STG_H) * 2;
        const uint32_t Vb = Kb + VH_H * 2;

        // ---- S = (Qh + Ql) Kh^T  (already scaled to base-2) ----
        float sf[8][4];
#pragma unroll
        for (int nf = 0; nf < 8; nf++)
#pragma unroll
            for (int q = 0; q < 4; q++) sf[nf][q] = 0.f;

#pragma unroll
        for (int ks = 0; ks < 8; ks++) {
            uint32_t ah[4], al[4];
            LDSM4(ah, q_off + ks * 32);
            LDSM4(al, q_off + ks * 32 + QL_H * 2);
#pragma unroll
            for (int np = 0; np < 4; np++) {
                uint32_t bo = Kb + ((np * 16 + k_row) * KROW + ks * 16 + k_ch) * 2;
                uint32_t b4h[4];
                LDSM4(b4h, bo);
#pragma unroll
                for (int half = 0; half < 2; half++) {
                    int nf = np * 2 + half;
                    mma16816(sf[nf], ah, b4h + half * 2);
                    mma16816(sf[nf], al, b4h + half * 2);
                }
            }
        }

        // ---- mask (skipped for fully-allowed interior tiles) ----
        const int kbase = kb * FKB;
        bool full = (kbase + FKB <= q0) && (sid[kbase] == sq_last);
        if (!full) {
#pragma unroll
            for (int nf = 0; nf < 8; nf++) {
                int c0 = kbase + nf * 8 + lt * 2;
                int sk0 = sid[c0], sk1 = sid[c0 + 1];
                if (c0 > qi0     || sk0 != sqr0) sf[nf][0] = -1.0e30f;
                if (c0 + 1 > qi0 || sk1 != sqr0) sf[nf][1] = -1.0e30f;
                if (c0 > qi1     || sk0 != sqr1) sf[nf][2] = -1.0e30f;
                if (c0 + 1 > qi1 || sk1 != sqr1) sf[nf][3] = -1.0e30f;
            }
        }

        // ---- online softmax (base-2, fp16x2 exp) ----
        float mx0 = -1.0e30f, mx1 = -1.0e30f;
#pragma unroll
        for (int nf = 0; nf < 8; nf++) {
            mx0 = fmaxf(mx0, fmaxf(sf[nf][0], sf[nf][1]));
            mx1 = fmaxf(mx1, fmaxf(sf[nf][2], sf[nf][3]));
        }
        mx0 = fmaxf(mx0, __shfl_xor_sync(0xffffffffu, mx0, 1));
        mx0 = fmaxf(mx0, __shfl_xor_sync(0xffffffffu, mx0, 2));
        mx1 = fmaxf(mx1, __shfl_xor_sync(0xffffffffu, mx1, 1));
        mx1 = fmaxf(mx1, __shfl_xor_sync(0xffffffffu, mx1, 2));
        float mn0 = fmaxf(m0, mx0), mn1 = fmaxf(m1, mx1);
        float a0 = ex2_f32(m0 - mn0), a1 = ex2_f32(m1 - mn1);
        float sum0 = 0.f, sum1 = 0.f;
        uint32_t ph[4][4];
#pragma unroll
        for (int nf = 0; nf < 8; nf++) {
            uint32_t e01 = ex2_f16x2(__floats2half2_rn(sf[nf][0] - mn0, sf[nf][1] - mn0));
            uint32_t e23 = ex2_f16x2(__floats2half2_rn(sf[nf][2] - mn1, sf[nf][3] - mn1));
            float2 f01 = __half22float2(*(__half2*)&e01);
            float2 f23 = __half22float2(*(__half2*)&e23);
            sum0 += f01.x + f01.y;
            sum1 += f23.x + f23.y;
            int ksv = nf >> 1, up = (nf & 1) ? 2 : 0;
            ph[ksv][up + 0] = e01;
            ph[ksv][up + 1] = e23;
        }
        sum0 += __shfl_xor_sync(0xffffffffu, sum0, 1);
        sum0 += __shfl_xor_sync(0xffffffffu, sum0, 2);
        sum1 += __shfl_xor_sync(0xffffffffu, sum1, 1);
        sum1 += __shfl_xor_sync(0xffffffffu, sum1, 2);
        l0 = l0 * a0 + sum0; m0 = mn0;
        l1 = l1 * a1 + sum1; m1 = mn1;

        // ---- rescale O, then O += P Vh ----
#pragma unroll
        for (int nf2 = 0; nf2 < 16; nf2++) {
            o[nf2][0] *= a0; o[nf2][1] *= a0;
            o[nf2][2] *= a1; o[nf2][3] *= a1;
        }
#pragma unroll
        for (int nf2 = 0; nf2 < 16; nf2++) {
            uint32_t vo = Vb + ((nf2 * 8 + v_row) * VROW + v_ch) * 2;
            uint32_t vh[8];
            LDSM4(vh, vo);
            LDSM4(vh + 4, vo + 64);
#pragma unroll
            for (int ksv = 0; ksv < 4; ksv++)
                mma16816(o[nf2], ph[ksv], vh + ksv * 2);
        }

        __syncthreads();
        if (kb + 2 <= kbe) F_ISSUE(kb + 2, st);
    }

    // ---- epilogue: fp16 output ----
    float i0 = 1.0f / l0, i1 = 1.0f / l1;
    int r0 = q0 + wid * 16 + lg;
#pragma unroll
    for (int nf2 = 0; nf2 < 16; nf2++) {
        int col = nf2 * 8 + lt * 2;
        size_t b0 = ((size_t)r0 * NH + h) * HD + col;
        size_t b1 = ((size_t)(r0 + 8) * NH + h) * HD + col;
        *(__half2*)(Aout + b0) = __floats2half2_rn(o[nf2][0] * i0, o[nf2][1] * i0);
        *(__half2*)(Aout + b1) = __floats2half2_rn(o[nf2][2] * i1, o[nf2][3] * i1);
    }
}

// ----------------------------------------------------------------
extern "C" void kernel_launch(void* const* d_in, const int* in_sizes, int n_in,
                              void* d_out, int out_size)
{
    const float* x   = (const float*)d_in[0];
    const float* wq  = (const float*)d_in[1];
    const float* wk  = (const float*)d_in[2];
    const float* wv  = (const float*)d_in[3];
    const float* wo  = (const float*)d_in[4];
    const float* fc  = (const float*)d_in[5];
    const float* fs  = (const float*)d_in[6];
    const int*   sid = (const int*)d_in[7];
    float* out = (float*)d_out;

    float *Vp;
    __half *xh, *ah, *wqkvh, *wqkvl, *woh;
    __half *qhp, *qlp, *khp, *vthp;
    cudaGetSymbolAddress((void**)&Vp, g_V);
    cudaGetSymbolAddress((void**)&xh, g_xh);
    cudaGetSymbolAddress((void**)&ah, g_ah);
    cudaGetSymbolAddress((void**)&wqkvh, g_wqkvh);
    cudaGetSymbolAddress((void**)&wqkvl, g_wqkvl);
    cudaGetSymbolAddress((void**)&woh, g_woh);
    cudaGetSymbolAddress((void**)&qhp, g_qh);
    cudaGetSymbolAddress((void**)&qlp, g_ql);
    cudaGetSymbolAddress((void**)&khp, g_kh);
    cudaGetSymbolAddress((void**)&vthp, g_vth);

    cudaFuncSetAttribute(gemm_hmma<0>, cudaFuncAttributeMaxDynamicSharedMemorySize, GEMM_SMEM);
    cudaFuncSetAttribute(gemm_hmma<1>, cudaFuncAttributeMaxDynamicSharedMemorySize, GEMM_SMEM);
    cudaFuncSetAttribute(flash_hmma, cudaFuncAttributeMaxDynamicSharedMemorySize, FLASH_SMEM);

    pack_hi<<<(T_TOK * DIM / 4 + 255) / 256, 256>>>(x, xh, T_TOK * DIM / 4);
    pack_w_all<<<dim3(DIM / 32, 160), 256>>>(wq, wk, wv, wo, wqkvh, wqkvl, woh);
    gemm_hmma<0><<<dim3(3072 / BN, T_TOK / BM), 256, GEMM_SMEM>>>(
        xh, wqkvh, wqkvl, qhp, qlp, khp, Vp, fc, fs);
    transpose_v<<<dim3(T_TOK / 32, HD / 32, NKV), 256>>>(Vp, vthp);
    flash_hmma<<<dim3(T_TOK / FQB, NH), 256, FLASH_SMEM>>>(
        qhp, qlp, khp, vthp, sid, ah);
    gemm_hmma<1><<<dim3(DIM / BN, T_TOK / BM), 256, GEMM_SMEM>>>(
        ah, woh, nullptr, nullptr, nullptr, nullptr, out, nullptr, nullptr);
}

// round 14
// speedup vs baseline: 1.5638x; 1.5638x over previous
#include <cuda_runtime.h>
#include <cuda_fp16.h>
#include <cstdint>
#include <math.h>

// ---------------- problem constants ----------------
#define T_TOK   4096
#define DIM     2048
#define NH      16
#define NKV     4
#define HD      128
#define QSCALE_LOG2E 0.12751744f   // 1/sqrt(128) * log2(e), absorbed into Q

// ---------------- HMMA GEMM constants ----------------
#define BM 128
#define BN 128
#define BK 32
#define GPAD 40
#define GBH_OFF (128 * GPAD)
#define GSTG_H  (GBH_OFF + 2 * 128 * GPAD)
#define STAGE_B (GSTG_H * 2)
#define NSTAGE 3
#define GEMM_SMEM (NSTAGE * STAGE_B)

// ---------------- flash constants ----------------
#define FQB  128
#define FKB  64
#define KROW 136
#define VROW 72
#define QL_H   (FQB * KROW)
#define STG0_H (2 * FQB * KROW)
#define VH_H   (FKB * KROW)
#define STG_H  (VH_H + HD * VROW)
#define FLASH_SMEM ((STG0_H + 2 * STG_H) * 2)

extern __shared__ __align__(16) char dyn_smem[];

// -------- scratch (device globals) --------
__device__ float  g_V[T_TOK * NKV * HD];
__device__ __half g_xh[T_TOK * DIM];
__device__ __half g_ah[T_TOK * DIM];
__device__ __half g_wqkvh[3072 * DIM], g_wqkvl[3072 * DIM];
__device__ __half g_woh[DIM * DIM];
__device__ __half g_qh[T_TOK * NH * HD],  g_ql[T_TOK * NH * HD];
__device__ __half g_kh[T_TOK * NKV * HD];
__device__ __half g_vth[NKV * HD * T_TOK];

// ---------------- helpers ----------------
__device__ __forceinline__ uint32_t smem_u32(const void* p) {
    uint32_t a;
    asm("{ .reg .u64 t; cvta.to.shared.u64 t, %1; cvt.u32.u64 %0, t; }" : "=r"(a) : "l"(p));
    return a;
}
__device__ __forceinline__ void cp16(void* dst, const void* src) {
    uint32_t d;
    asm("{ .reg .u64 t; cvta.to.shared.u64 t, %1; cvt.u32.u64 %0, t; }" : "=r"(d) : "l"(dst));
    asm volatile("cp.async.cg.shared.global [%0], [%1], 16;" :: "r"(d), "l"(src));
}
__device__ __forceinline__ void mma16816(float* c, const uint32_t* a, const uint32_t* b) {
    asm volatile(
        "mma.sync.aligned.m16n8k16.row.col.f32.f16.f16.f32 "
        "{%0,%1,%2,%3}, {%4,%5,%6,%7}, {%8,%9}, {%0,%1,%2,%3};"
        : "+f"(c[0]), "+f"(c[1]), "+f"(c[2]), "+f"(c[3])
        : "r"(a[0]), "r"(a[1]), "r"(a[2]), "r"(a[3]), "r"(b[0]), "r"(b[1]));
}
#define LDSM4(R, a) \
    asm volatile("ldmatrix.sync.aligned.m8n8.x4.shared.b16 {%0,%1,%2,%3}, [%4];" \
        : "=r"((R)[0]), "=r"((R)[1]), "=r"((R)[2]), "=r"((R)[3]) : "r"(a))
__device__ __forceinline__ uint32_t ex2_f16x2(__half2 x) {
    uint32_t r;
    asm("ex2.approx.f16x2 %0, %1;" : "=r"(r) : "r"(*(uint32_t*)&x));
    return r;
}
__device__ __forceinline__ float ex2_f32(float x) {
    float r;
    asm("ex2.approx.f32 %0, %1;" : "=f"(r) : "f"(x));
    return r;
}

// ---------------- pack x: fp32 -> hi fp16 ----------------
__global__ void __launch_bounds__(256) pack_hi(const float* __restrict__ in,
                                               __half* __restrict__ oh, int n4) {
    int i = blockIdx.x * blockDim.x + threadIdx.x;
    if (i >= n4) return;
    float4 v = ((const float4*)in)[i];
    ((__half2*)oh)[i * 2 + 0] = __floats2half2_rn(v.x, v.y);
    ((__half2*)oh)[i * 2 + 1] = __floats2half2_rn(v.z, v.w);
}

// ---------------- fused weight transpose+split ----------------
__global__ void __launch_bounds__(256) pack_w_all(const float* __restrict__ wq,
                                                  const float* __restrict__ wk,
                                                  const float* __restrict__ wv,
                                                  const float* __restrict__ wo,
                                                  __half* __restrict__ qkvh,
                                                  __half* __restrict__ qkvl,
                                                  __half* __restrict__ woh) {
    __shared__ float t[32][33];
    int k0 = blockIdx.x * 32;
    int by = blockIdx.y;
    const float* w; __half *oh, *ol;
    int Nsrc, nbase, n0;
    if (by < 64)       { w = wq; Nsrc = 2048; nbase = 0;    n0 = by * 32;        oh = qkvh; ol = qkvl; }
    else if (by < 80)  { w = wk; Nsrc = 512;  nbase = 2048; n0 = (by - 64) * 32; oh = qkvh; ol = qkvl; }
    else if (by < 96)  { w = wv; Nsrc = 512;  nbase = 2560; n0 = (by - 80) * 32; oh = qkvh; ol = qkvl; }
    else               { w = wo; Nsrc = 2048; nbase = 0;    n0 = (by - 96) * 32; oh = woh;  ol = nullptr; }
    int tid = threadIdx.x;
    int cc = tid & 31, rr = tid >> 5;
#pragma unroll
    for (int i = 0; i < 4; i++) {
        int row = rr + i * 8;
        t[row][cc] = w[(size_t)(k0 + row) * Nsrc + n0 + cc];
    }
    __syncthreads();
#pragma unroll
    for (int i = 0; i < 4; i++) {
        int n = rr + i * 8;
        float v = t[cc][n];
        __half h = __float2half_rn(v);
        size_t o = (size_t)(nbase + n0 + n) * DIM + k0 + cc;
        oh[o] = h;
        if (ol) ol[o] = __float2half_rn(v - __half2float(h));
    }
}

// ---------------- HMMA GEMM — MODE/USE_LO are compile-time ----------------
// MODE 0: QKV epilogue (RoPE on Q/K, V fp32); MODE 1: plain fp32 output.
// USE_LO 1: 2-product (Bh+Bl); USE_LO 0: 1-product (Bh).
// nt0: column-tile offset (in units of BN).
template<int MODE, int USE_LO>
__global__ void __launch_bounds__(256, 2) gemm_hmma(const __half* __restrict__ Ah,
                                                    const __half* __restrict__ Bh,
                                                    const __half* __restrict__ Bl,
                                                    __half* __restrict__ qh,
                                                    __half* __restrict__ ql,
                                                    __half* __restrict__ kh,
                                                    float* __restrict__ Vout,
                                                    const float* __restrict__ fc,
                                                    const float* __restrict__ fs,
                                                    int nt0) {
    __half* sm = (__half*)dyn_smem;
    const int tid = threadIdx.x;
    const int wid = tid >> 5, lane = tid & 31;
    const int wm = (wid & 1) * 64, wn = (wid >> 1) * 32;
    const int lg = lane >> 2, lt = lane & 3;

    const int ntile = nt0 + blockIdx.x;
    const size_t arow0 = (size_t)blockIdx.y * BM;
    const size_t brow0 = (size_t)ntile * BN;
    constexpr int NCOPY = USE_LO ? 6 : 4;

    float acc[4][4][4];
#pragma unroll
    for (int mf = 0; mf < 4; mf++)
#pragma unroll
        for (int nf = 0; nf < 4; nf++)
#pragma unroll
            for (int q = 0; q < 4; q++) acc[mf][nf][q] = 0.f;

    const int NKT = DIM / BK;

#define G_ISSUE(KT, ST) do {                                                     \
    __half* _sb = sm + (ST) * GSTG_H;                                            \
    int _k0 = (KT) * BK;                                                         \
    _Pragma("unroll")                                                            \
    for (int _i = 0; _i < NCOPY; _i++) {                                         \
        int _idx = tid + _i * 256;                                               \
        if (_idx < 512) {                                                        \
            int _row = _idx >> 2, _ch = _idx & 3;                                \
            cp16(_sb + _row * GPAD + _ch * 8,                                    \
                 Ah + (arow0 + _row) * DIM + _k0 + _ch * 8);                     \
        } else {                                                                 \
            int _j = _idx - 512;                                                 \
            int _sp = _j >> 9, _rem = _j & 511;                                  \
            int _row = _rem >> 2, _ch = _rem & 3;                                \
            const __half* _src = (_sp ? Bl : Bh)                                 \
                + (brow0 + _row) * DIM + _k0 + _ch * 8;                          \
            cp16(_sb + GBH_OFF + _sp * (128 * GPAD) + _row * GPAD + _ch * 8, _src); \
        }                                                                        \
    }                                                                            \
    asm volatile("cp.async.commit_group;" ::: "memory");                         \
} while (0)

    G_ISSUE(0, 0);
    G_ISSUE(1, 1);

    const uint32_t smb = smem_u32(sm);
    const int a_row = (lane & 15);
    const int a_ch  = (lane >> 4) * 8;
    const int b_row = ((lane >> 4) & 1) * 8 + (lane & 7);
    const int b_ch  = ((lane >> 3) & 1) * 8;

    for (int kt = 0; kt < NKT; kt++) {
        int st = kt % NSTAGE;
        if (kt + 1 < NKT) asm volatile("cp.async.wait_group 1;" ::: "memory");
        else              asm volatile("cp.async.wait_group 0;" ::: "memory");
        __syncthreads();
        if (kt + 2 < NKT) G_ISSUE(kt + 2, (kt + 2) % NSTAGE);

        const uint32_t sb = smb + st * STAGE_B;

#pragma unroll
        for (int ks = 0; ks < 2; ks++) {
            uint32_t ah[4][4];
#pragma unroll
            for (int mf = 0; mf < 4; mf++) {
                uint32_t ao = sb + ((wm + mf * 16 + a_row) * GPAD + ks * 16 + a_ch) * 2;
                LDSM4(ah[mf], ao);
            }
#pragma unroll
            for (int np = 0; np < 2; np++) {
                uint32_t bo = sb + (GBH_OFF + (wn + np * 16 + b_row) * GPAD + ks * 16 + b_ch) * 2;
                uint32_t b4h[4], b4l[4];
                LDSM4(b4h, bo);
                if (USE_LO) LDSM4(b4l, bo + (128 * GPAD) * 2);
#pragma unroll
                for (int half = 0; half < 2; half++) {
                    int nf = np * 2 + half;
#pragma unroll
                    for (int mf = 0; mf < 4; mf++) {
                        mma16816(acc[mf][nf], ah[mf], b4h + half * 2);
                        if (USE_LO) mma16816(acc[mf][nf], ah[mf], b4l + half * 2);
                    }
                }
            }
        }
    }

    // ---- epilogue ----
    const int nblock = ntile * BN;
#pragma unroll
    for (int mf = 0; mf < 4; mf++) {
        size_t row0 = arow0 + wm + mf * 16 + lg;
        size_t row1 = row0 + 8;
#pragma unroll
        for (int nf = 0; nf < 4; nf++) {
            int ncol = nblock + wn + nf * 8 + lt * 2;
            if (MODE == 1) {
                *(float2*)(Vout + row0 * 2048 + ncol) = make_float2(acc[mf][nf][0], acc[mf][nf][1]);
                *(float2*)(Vout + row1 * 2048 + ncol) = make_float2(acc[mf][nf][2], acc[mf][nf][3]);
            } else if (ncol < 2048) {
                int pair = (ncol & 127) >> 1;
                float c0 = fc[row0 * 64 + pair], s0 = fs[row0 * 64 + pair];
                float c1 = fc[row1 * 64 + pair], s1 = fs[row1 * 64 + pair];
                float q00 = (acc[mf][nf][0] * c0 - acc[mf][nf][1] * s0) * QSCALE_LOG2E;
                float q01 = (acc[mf][nf][0] * s0 + acc[mf][nf][1] * c0) * QSCALE_LOG2E;
                float q10 = (acc[mf][nf][2] * c1 - acc[mf][nf][3] * s1) * QSCALE_LOG2E;
                float q11 = (acc[mf][nf][2] * s1 + acc[mf][nf][3] * c1) * QSCALE_LOG2E;
                __half2 h0 = __floats2half2_rn(q00, q01);
                __half2 h1 = __floats2half2_rn(q10, q11);
                float2 f0 = __half22float2(h0), f1 = __half22float2(h1);
                *(__half2*)(qh + row0 * 2048 + ncol) = h0;
                *(__half2*)(qh + row1 * 2048 + ncol) = h1;
                *(__half2*)(ql + row0 * 2048 + ncol) = __floats2half2_rn(q00 - f0.x, q01 - f0.y);
                *(__half2*)(ql + row1 * 2048 + ncol) = __floats2half2_rn(q10 - f1.x, q11 - f1.y);
            } else if (ncol < 2560) {
                int kcol = ncol - 2048;
                int pair = (kcol & 127) >> 1;
                float c0 = fc[row0 * 64 + pair], s0 = fs[row0 * 64 + pair];
                float c1 = fc[row1 * 64 + pair], s1 = fs[row1 * 64 + pair];
                float k00 = acc[mf][nf][0] * c0 - acc[mf][nf][1] * s0;
                float k01 = acc[mf][nf][0] * s0 + acc[mf][nf][1] * c0;
                float k10 = acc[mf][nf][2] * c1 - acc[mf][nf][3] * s1;
                float k11 = acc[mf][nf][2] * s1 + acc[mf][nf][3] * c1;
                *(__half2*)(kh + row0 * 512 + kcol) = __floats2half2_rn(k00, k01);
                *(__half2*)(kh + row1 * 512 + kcol) = __floats2half2_rn(k10, k11);
            } else {
                int vcol = ncol - 2560;
                *(float2*)(Vout + row0 * 512 + vcol) = make_float2(acc[mf][nf][0], acc[mf][nf][1]);
                *(float2*)(Vout + row1 * 512 + vcol) = make_float2(acc[mf][nf][2], acc[mf][nf][3]);
            }
        }
    }
}

// ---------------- V transpose (hi only) ----------------
__global__ void __launch_bounds__(256) transpose_v(const float* __restrict__ V,
                                                   __half* __restrict__ vth)
{
    __shared__ float t[32][33];
    int kv = blockIdx.z, t0 = blockIdx.x * 32, d0 = blockIdx.y * 32;
    int cc = threadIdx.x & 31, rr = threadIdx.x >> 5;
#pragma unroll
    for (int i = 0; i < 4; i++) {
        int tok = rr + i * 8;
        t[tok][cc] = V[((size_t)(t0 + tok) * NKV + kv) * HD + d0 + cc];
    }
    __syncthreads();
#pragma unroll
    for (int i = 0; i < 4; i++) {
        int dd = rr + i * 8;
        size_t o = ((size_t)kv * HD + d0 + dd) * T_TOK + t0 + cc;
        vth[o] = __float2half_rn(t[cc][dd]);
    }
}

// ---------------- flash attention: base-2 scores, f16x2 exp ----------------
__global__ void __launch_bounds__(256) flash_hmma(
    const __half* __restrict__ qh, const __half* __restrict__ ql,
    const __half* __restrict__ kh, const __half* __restrict__ vth,
    const int* __restrict__ sid, __half* __restrict__ Aout)
{
    __half* S = (__half*)dyn_smem;
    const int tid = threadIdx.x, wid = tid >> 5, lane = tid & 31;
    const int lg = lane >> 2, lt = lane & 3;
    const int h = blockIdx.y, kv = h >> 2;
    const int q0 = (gridDim.x - 1 - blockIdx.x) * FQB;

#pragma unroll
    for (int i = 0; i < 16; i++) {
        int id = tid + i * 256;
        int sp = id >> 11, rem = id & 2047;
        int row = rem >> 4, ch = rem & 15;
        const __half* src = (sp ? ql : qh) + ((size_t)(q0 + row) * NH + h) * HD + ch * 8;
        cp16(S + sp * QL_H + row * KROW + ch * 8, src);
    }
    asm volatile("cp.async.commit_group;" ::: "memory");

#define F_ISSUE(KB, ST) do {                                                          \
    __half* _s = S + STG0_H + (ST) * STG_H;                                           \
    int _t0 = (KB) * FKB;                                                             \
    _Pragma("unroll")                                                                 \
    for (int _i = 0; _i < 4; _i++) {                                                  \
        int _id = tid + _i * 256;                                                     \
        int _row = _id >> 4, _ch = _id & 15;                                          \
        cp16(_s + _row * KROW + _ch * 8,                                              \
             kh + ((size_t)(_t0 + _row) * NKV + kv) * HD + _ch * 8);                  \
    }                                                                                 \
    _Pragma("unroll")                                                                 \
    for (int _i = 0; _i < 4; _i++) {                                                  \
        int _id = tid + _i * 256;                                                     \
        int _row = _id >> 3, _ch = _id & 7;                                           \
        cp16(_s + VH_H + _row * VROW + _ch * 8,                                       \
             vth + ((size_t)kv * HD + _row) * T_TOK + _t0 + _ch * 8);                 \
    }                                                                                 \
    asm volatile("cp.async.commit_group;" ::: "memory");                              \
} while (0)

    const int qi0 = q0 + wid * 16 + lg, qi1 = qi0 + 8;
    const int sqr0 = sid[qi0], sqr1 = sid[qi1];
    const int sq_first = sid[q0];
    const int sq_last  = sid[q0 + FQB - 1];
    const int kbe = q0 / FKB + 1;
    int kb0 = kbe;
    for (int kb = 0; kb <= kbe; kb++) {
        if (sid[kb * FKB + FKB - 1] >= sq_first) { kb0 = kb; break; }
    }

    F_ISSUE(kb0, 0);
    if (kb0 + 1 <= kbe) F_ISSUE(kb0 + 1, 1);

    float o[16][4];
#pragma unroll
    for (int i = 0; i < 16; i++)
#pragma unroll
        for (int j = 0; j < 4; j++) o[i][j] = 0.f;
    float m0 = -1.0e30f, l0 = 0.f, m1 = -1.0e30f, l1 = 0.f;

    const uint32_t Sb = smem_u32(S);
    const uint32_t q_off = Sb + (((wid * 16 + (lane & 15)) * KROW) + (lane >> 4) * 8) * 2;
    const int k_row = ((lane >> 4) & 1) * 8 + (lane & 7);
    const int k_ch  = ((lane >> 3) & 1) * 8;
    const int v_row = lane & 7;
    const int v_ch  = (lane >> 3) * 8;

    for (int kb = kb0; kb <= kbe; kb++) {
        int st = (kb - kb0) & 1;
        if (kb + 1 <= kbe) asm volatile("cp.async.wait_group 1;" ::: "memory");
        else               asm volatile("cp.async.wait_group 0;" ::: "memory");
        __syncthreads();

        const uint32_t Kb = Sb + (STG0_H + st * STG_H) * 2;
        const uint32_t Vb = Kb + VH_H * 2;

        // ---- S = (Qh + Ql) Kh^T ----
        float sf[8][4];
#pragma unroll
        for (int nf = 0; nf < 8; nf++)
#pragma unroll
            for (int q = 0; q < 4; q++) sf[nf][q] = 0.f;

#pragma unroll
        for (int ks = 0; ks < 8; ks++) {
            uint32_t ah[4], al[4];
            LDSM4(ah, q_off + ks * 32);
            LDSM4(al, q_off + ks * 32 + QL_H * 2);
#pragma unroll
            for (int np = 0; np < 4; np++) {
                uint32_t bo = Kb + ((np * 16 + k_row) * KROW + ks * 16 + k_ch) * 2;
                uint32_t b4h[4];
                LDSM4(b4h, bo);
#pragma unroll
                for (int half = 0; half < 2; half++) {
                    int nf = np * 2 + half;
                    mma16816(sf[nf], ah, b4h + half * 2);
                    mma16816(sf[nf], al, b4h + half * 2);
                }
            }
        }

        // ---- mask (skipped for fully-allowed interior tiles) ----
        const int kbase = kb * FKB;
        bool full = (kbase + FKB <= q0) && (sid[kbase] == sq_last);
        if (!full) {
#pragma unroll
            for (int nf = 0; nf < 8; nf++) {
                int c0 = kbase + nf * 8 + lt * 2;
                int sk0 = sid[c0], sk1 = sid[c0 + 1];
                if (c0 > qi0     || sk0 != sqr0) sf[nf][0] = -1.0e30f;
                if (c0 + 1 > qi0 || sk1 != sqr0) sf[nf][1] = -1.0e30f;
                if (c0 > qi1     || sk0 != sqr1) sf[nf][2] = -1.0e30f;
                if (c0 + 1 > qi1 || sk1 != sqr1) sf[nf][3] = -1.0e30f;
            }
        }

        // ---- online softmax (base-2, fp16x2 exp) ----
        float mx0 = -1.0e30f, mx1 = -1.0e30f;
#pragma unroll
        for (int nf = 0; nf < 8; nf++) {
            mx0 = fmaxf(mx0, fmaxf(sf[nf][0], sf[nf][1]));
            mx1 = fmaxf(mx1, fmaxf(sf[nf][2], sf[nf][3]));
        }
        mx0 = fmaxf(mx0, __shfl_xor_sync(0xffffffffu, mx0, 1));
        mx0 = fmaxf(mx0, __shfl_xor_sync(0xffffffffu, mx0, 2));
        mx1 = fmaxf(mx1, __shfl_xor_sync(0xffffffffu, mx1, 1));
        mx1 = fmaxf(mx1, __shfl_xor_sync(0xffffffffu, mx1, 2));
        float mn0 = fmaxf(m0, mx0), mn1 = fmaxf(m1, mx1);
        float a0 = ex2_f32(m0 - mn0), a1 = ex2_f32(m1 - mn1);
        float sum0 = 0.f, sum1 = 0.f;
        uint32_t ph[4][4];
#pragma unroll
        for (int nf = 0; nf < 8; nf++) {
            uint32_t e01 = ex2_f16x2(__floats2half2_rn(sf[nf][0] - mn0, sf[nf][1] - mn0));
            uint32_t e23 = ex2_f16x2(__floats2half2_rn(sf[nf][2] - mn1, sf[nf][3] - mn1));
            float2 f01 = __half22float2(*(__half2*)&e01);
            float2 f23 = __half22float2(*(__half2*)&e23);
            sum0 += f01.x + f01.y;
            sum1 += f23.x + f23.y;
            int ksv = nf >> 1, up = (nf & 1) ? 2 : 0;
            ph[ksv][up + 0] = e01;
            ph[ksv][up + 1] = e23;
        }
        sum0 += __shfl_xor_sync(0xffffffffu, sum0, 1);
        sum0 += __shfl_xor_sync(0xffffffffu, sum0, 2);
        sum1 += __shfl_xor_sync(0xffffffffu, sum1, 1);
        sum1 += __shfl_xor_sync(0xffffffffu, sum1, 2);
        l0 = l0 * a0 + sum0; m0 = mn0;
        l1 = l1 * a1 + sum1; m1 = mn1;

        // ---- rescale O, then O += P Vh ----
#pragma unroll
        for (int nf2 = 0; nf2 < 16; nf2++) {
            o[nf2][0] *= a0; o[nf2][1] *= a0;
            o[nf2][2] *= a1; o[nf2][3] *= a1;
        }
#pragma unroll
        for (int nf2 = 0; nf2 < 16; nf2++) {
            uint32_t vo = Vb + ((nf2 * 8 + v_row) * VROW + v_ch) * 2;
            uint32_t vh[8];
            LDSM4(vh, vo);
            LDSM4(vh + 4, vo + 64);
#pragma unroll
            for (int ksv = 0; ksv < 4; ksv++)
                mma16816(o[nf2], ph[ksv], vh + ksv * 2);
        }

        __syncthreads();
        if (kb + 2 <= kbe) F_ISSUE(kb + 2, st);
    }

    // ---- epilogue: fp16 output ----
    float i0 = 1.0f / l0, i1 = 1.0f / l1;
    int r0 = q0 + wid * 16 + lg;
#pragma unroll
    for (int nf2 = 0; nf2 < 16; nf2++) {
        int col = nf2 * 8 + lt * 2;
        size_t b0 = ((size_t)r0 * NH + h) * HD + col;
        size_t b1 = ((size_t)(r0 + 8) * NH + h) * HD + col;
        *(__half2*)(Aout + b0) = __floats2half2_rn(o[nf2][0] * i0, o[nf2][1] * i0);
        *(__half2*)(Aout + b1) = __floats2half2_rn(o[nf2][2] * i1, o[nf2][3] * i1);
    }
}

// ----------------------------------------------------------------
extern "C" void kernel_launch(void* const* d_in, const int* in_sizes, int n_in,
                              void* d_out, int out_size)
{
    const float* x   = (const float*)d_in[0];
    const float* wq  = (const float*)d_in[1];
    const float* wk  = (const float*)d_in[2];
    const float* wv  = (const float*)d_in[3];
    const float* wo  = (const float*)d_in[4];
    const float* fc  = (const float*)d_in[5];
    const float* fs  = (const float*)d_in[6];
    const int*   sid = (const int*)d_in[7];
    float* out = (float*)d_out;

    float *Vp;
    __half *xh, *ah, *wqkvh, *wqkvl, *woh;
    __half *qhp, *qlp, *khp, *vthp;
    cudaGetSymbolAddress((void**)&Vp, g_V);
    cudaGetSymbolAddress((void**)&xh, g_xh);
    cudaGetSymbolAddress((void**)&ah, g_ah);
    cudaGetSymbolAddress((void**)&wqkvh, g_wqkvh);
    cudaGetSymbolAddress((void**)&wqkvl, g_wqkvl);
    cudaGetSymbolAddress((void**)&woh, g_woh);
    cudaGetSymbolAddress((void**)&qhp, g_qh);
    cudaGetSymbolAddress((void**)&qlp, g_ql);
    cudaGetSymbolAddress((void**)&khp, g_kh);
    cudaGetSymbolAddress((void**)&vthp, g_vth);

    cudaFuncSetAttribute((const void*)gemm_hmma<0,1>, cudaFuncAttributeMaxDynamicSharedMemorySize, GEMM_SMEM);
    cudaFuncSetAttribute((const void*)gemm_hmma<0,0>, cudaFuncAttributeMaxDynamicSharedMemorySize, GEMM_SMEM);
    cudaFuncSetAttribute((const void*)gemm_hmma<1,0>, cudaFuncAttributeMaxDynamicSharedMemorySize, GEMM_SMEM);
    cudaFuncSetAttribute((const void*)flash_hmma, cudaFuncAttributeMaxDynamicSharedMemorySize, FLASH_SMEM);

    pack_hi<<<(T_TOK * DIM / 4 + 255) / 256, 256>>>(x, xh, T_TOK * DIM / 4);
    pack_w_all<<<dim3(DIM / 32, 160), 256>>>(wq, wk, wv, wo, wqkvh, wqkvl, woh);

    // Q projection: 2-product, tiles 0..15
    gemm_hmma<0,1><<<dim3(16, T_TOK / BM), 256, GEMM_SMEM>>>(
        xh, wqkvh, wqkvl, qhp, qlp, khp, Vp, fc, fs, 0);
    // K/V projection: 1-product, tiles 16..23
    gemm_hmma<0,0><<<dim3(8, T_TOK / BM), 256, GEMM_SMEM>>>(
        xh, wqkvh, wqkvl, qhp, qlp, khp, Vp, fc, fs, 16);

    transpose_v<<<dim3(T_TOK / 32, HD / 32, NKV), 256>>>(Vp, vthp);
    flash_hmma<<<dim3(T_TOK / FQB, NH), 256, FLASH_SMEM>>>(
        qhp, qlp, khp, vthp, sid, ah);
    gemm_hmma<1,0><<<dim3(DIM / BN, T_TOK / BM), 256, GEMM_SMEM>>>(
        ah, woh, nullptr, nullptr, nullptr, nullptr, out, nullptr, nullptr, 0);
}

// round 15
// speedup vs baseline: 1.5991x; 1.0226x over previous
#include <cuda_runtime.h>
#include <cuda_fp16.h>
#include <cstdint>
#include <math.h>

// ---------------- problem constants ----------------
#define T_TOK   4096
#define DIM     2048
#define NH      16
#define NKV     4
#define HD      128
#define QSCALE_LOG2E 0.12751744f   // 1/sqrt(128) * log2(e), absorbed into Q

// ---------------- HMMA GEMM constants ----------------
#define BM 128
#define BN 128
#define BK 32
#define GPAD 40
#define GBH_OFF (128 * GPAD)
#define GSTG_H  (GBH_OFF + 2 * 128 * GPAD)
#define STAGE_B (GSTG_H * 2)
#define NSTAGE 3
#define GEMM_SMEM (NSTAGE * STAGE_B)

// ---------------- flash constants (FKB=128, processed as 2x64 halves) ----------------
#define FQB  128
#define FKB  128
#define KROW 136
#define QL_H   (FQB * KROW)            // 17408
#define STG0_H (2 * QL_H)              // 34816 (Q hi+lo)
#define KT_H   (FKB * KROW)            // 17408 (K tile)
#define STG_H  (2 * KT_H)              // 34816 (K + V)
#define FLASH_SMEM ((STG0_H + 2 * STG_H) * 2)   // 208896 B

extern __shared__ __align__(16) char dyn_smem[];

// -------- scratch (device globals) --------
__device__ float  g_V[T_TOK * NKV * HD];
__device__ __half g_xh[T_TOK * DIM];
__device__ __half g_ah[T_TOK * DIM];
__device__ __half g_wqkvh[3072 * DIM], g_wqkvl[3072 * DIM];
__device__ __half g_woh[DIM * DIM];
__device__ __half g_qh[T_TOK * NH * HD],  g_ql[T_TOK * NH * HD];
__device__ __half g_kh[T_TOK * NKV * HD];
__device__ __half g_vth[NKV * HD * T_TOK];

// ---------------- helpers ----------------
__device__ __forceinline__ uint32_t smem_u32(const void* p) {
    uint32_t a;
    asm("{ .reg .u64 t; cvta.to.shared.u64 t, %1; cvt.u32.u64 %0, t; }" : "=r"(a) : "l"(p));
    return a;
}
__device__ __forceinline__ void cp16(void* dst, const void* src) {
    uint32_t d;
    asm("{ .reg .u64 t; cvta.to.shared.u64 t, %1; cvt.u32.u64 %0, t; }" : "=r"(d) : "l"(dst));
    asm volatile("cp.async.cg.shared.global [%0], [%1], 16;" :: "r"(d), "l"(src));
}
__device__ __forceinline__ void mma16816(float* c, const uint32_t* a, const uint32_t* b) {
    asm volatile(
        "mma.sync.aligned.m16n8k16.row.col.f32.f16.f16.f32 "
        "{%0,%1,%2,%3}, {%4,%5,%6,%7}, {%8,%9}, {%0,%1,%2,%3};"
        : "+f"(c[0]), "+f"(c[1]), "+f"(c[2]), "+f"(c[3])
        : "r"(a[0]), "r"(a[1]), "r"(a[2]), "r"(a[3]), "r"(b[0]), "r"(b[1]));
}
#define LDSM4(R, a) \
    asm volatile("ldmatrix.sync.aligned.m8n8.x4.shared.b16 {%0,%1,%2,%3}, [%4];" \
        : "=r"((R)[0]), "=r"((R)[1]), "=r"((R)[2]), "=r"((R)[3]) : "r"(a))
__device__ __forceinline__ uint32_t ex2_f16x2(__half2 x) {
    uint32_t r;
    asm("ex2.approx.f16x2 %0, %1;" : "=r"(r) : "r"(*(uint32_t*)&x));
    return r;
}
__device__ __forceinline__ float ex2_f32(float x) {
    float r;
    asm("ex2.approx.f32 %0, %1;" : "=f"(r) : "f"(x));
    return r;
}

// ---------------- pack x: fp32 -> hi fp16 ----------------
__global__ void __launch_bounds__(256) pack_hi(const float* __restrict__ in,
                                               __half* __restrict__ oh, int n4) {
    int i = blockIdx.x * blockDim.x + threadIdx.x;
    if (i >= n4) return;
    float4 v = ((const float4*)in)[i];
    ((__half2*)oh)[i * 2 + 0] = __floats2half2_rn(v.x, v.y);
    ((__half2*)oh)[i * 2 + 1] = __floats2half2_rn(v.z, v.w);
}

// ---------------- fused weight transpose+split ----------------
__global__ void __launch_bounds__(256) pack_w_all(const float* __restrict__ wq,
                                                  const float* __restrict__ wk,
                                                  const float* __restrict__ wv,
                                                  const float* __restrict__ wo,
                                                  __half* __restrict__ qkvh,
                                                  __half* __restrict__ qkvl,
                                                  __half* __restrict__ woh) {
    __shared__ float t[32][33];
    int k0 = blockIdx.x * 32;
    int by = blockIdx.y;
    const float* w; __half *oh, *ol;
    int Nsrc, nbase, n0;
    if (by < 64)       { w = wq; Nsrc = 2048; nbase = 0;    n0 = by * 32;        oh = qkvh; ol = qkvl; }
    else if (by < 80)  { w = wk; Nsrc = 512;  nbase = 2048; n0 = (by - 64) * 32; oh = qkvh; ol = qkvl; }
    else if (by < 96)  { w = wv; Nsrc = 512;  nbase = 2560; n0 = (by - 80) * 32; oh = qkvh; ol = qkvl; }
    else               { w = wo; Nsrc = 2048; nbase = 0;    n0 = (by - 96) * 32; oh = woh;  ol = nullptr; }
    int tid = threadIdx.x;
    int cc = tid & 31, rr = tid >> 5;
#pragma unroll
    for (int i = 0; i < 4; i++) {
        int row = rr + i * 8;
        t[row][cc] = w[(size_t)(k0 + row) * Nsrc + n0 + cc];
    }
    __syncthreads();
#pragma unroll
    for (int i = 0; i < 4; i++) {
        int n = rr + i * 8;
        float v = t[cc][n];
        __half h = __float2half_rn(v);
        size_t o = (size_t)(nbase + n0 + n) * DIM + k0 + cc;
        oh[o] = h;
        if (ol) ol[o] = __float2half_rn(v - __half2float(h));
    }
}

// ---------------- HMMA GEMM — MODE/USE_LO compile-time (unchanged from R14) ----------------
template<int MODE, int USE_LO>
__global__ void __launch_bounds__(256, 2) gemm_hmma(const __half* __restrict__ Ah,
                                                    const __half* __restrict__ Bh,
                                                    const __half* __restrict__ Bl,
                                                    __half* __restrict__ qh,
                                                    __half* __restrict__ ql,
                                                    __half* __restrict__ kh,
                                                    float* __restrict__ Vout,
                                                    const float* __restrict__ fc,
                                                    const float* __restrict__ fs,
                                                    int nt0) {
    __half* sm = (__half*)dyn_smem;
    const int tid = threadIdx.x;
    const int wid = tid >> 5, lane = tid & 31;
    const int wm = (wid & 1) * 64, wn = (wid >> 1) * 32;
    const int lg = lane >> 2, lt = lane & 3;

    const int ntile = nt0 + blockIdx.x;
    const size_t arow0 = (size_t)blockIdx.y * BM;
    const size_t brow0 = (size_t)ntile * BN;
    constexpr int NCOPY = USE_LO ? 6 : 4;

    float acc[4][4][4];
#pragma unroll
    for (int mf = 0; mf < 4; mf++)
#pragma unroll
        for (int nf = 0; nf < 4; nf++)
#pragma unroll
            for (int q = 0; q < 4; q++) acc[mf][nf][q] = 0.f;

    const int NKT = DIM / BK;

#define G_ISSUE(KT, ST) do {                                                     \
    __half* _sb = sm + (ST) * GSTG_H;                                            \
    int _k0 = (KT) * BK;                                                         \
    _Pragma("unroll")                                                            \
    for (int _i = 0; _i < NCOPY; _i++) {                                         \
        int _idx = tid + _i * 256;                                               \
        if (_idx < 512) {                                                        \
            int _row = _idx >> 2, _ch = _idx & 3;                                \
            cp16(_sb + _row * GPAD + _ch * 8,                                    \
                 Ah + (arow0 + _row) * DIM + _k0 + _ch * 8);                     \
        } else {                                                                 \
            int _j = _idx - 512;                                                 \
            int _sp = _j >> 9, _rem = _j & 511;                                  \
            int _row = _rem >> 2, _ch = _rem & 3;                                \
            const __half* _src = (_sp ? Bl : Bh)                                 \
                + (brow0 + _row) * DIM + _k0 + _ch * 8;                          \
            cp16(_sb + GBH_OFF + _sp * (128 * GPAD) + _row * GPAD + _ch * 8, _src); \
        }                                                                        \
    }                                                                            \
    asm volatile("cp.async.commit_group;" ::: "memory");                         \
} while (0)

    G_ISSUE(0, 0);
    G_ISSUE(1, 1);

    const uint32_t smb = smem_u32(sm);
    const int a_row = (lane & 15);
    const int a_ch  = (lane >> 4) * 8;
    const int b_row = ((lane >> 4) & 1) * 8 + (lane & 7);
    const int b_ch  = ((lane >> 3) & 1) * 8;

    for (int kt = 0; kt < NKT; kt++) {
        int st = kt % NSTAGE;
        if (kt + 1 < NKT) asm volatile("cp.async.wait_group 1;" ::: "memory");
        else              asm volatile("cp.async.wait_group 0;" ::: "memory");
        __syncthreads();
        if (kt + 2 < NKT) G_ISSUE(kt + 2, (kt + 2) % NSTAGE);

        const uint32_t sb = smb + st * STAGE_B;

#pragma unroll
        for (int ks = 0; ks < 2; ks++) {
            uint32_t ah[4][4];
#pragma unroll
            for (int mf = 0; mf < 4; mf++) {
                uint32_t ao = sb + ((wm + mf * 16 + a_row) * GPAD + ks * 16 + a_ch) * 2;
                LDSM4(ah[mf], ao);
            }
#pragma unroll
            for (int np = 0; np < 2; np++) {
                uint32_t bo = sb + (GBH_OFF + (wn + np * 16 + b_row) * GPAD + ks * 16 + b_ch) * 2;
                uint32_t b4h[4], b4l[4];
                LDSM4(b4h, bo);
                if (USE_LO) LDSM4(b4l, bo + (128 * GPAD) * 2);
#pragma unroll
                for (int half = 0; half < 2; half++) {
                    int nf = np * 2 + half;
#pragma unroll
                    for (int mf = 0; mf < 4; mf++) {
                        mma16816(acc[mf][nf], ah[mf], b4h + half * 2);
                        if (USE_LO) mma16816(acc[mf][nf], ah[mf], b4l + half * 2);
                    }
                }
            }
        }
    }

    // ---- epilogue ----
    const int nblock = ntile * BN;
#pragma unroll
    for (int mf = 0; mf < 4; mf++) {
        size_t row0 = arow0 + wm + mf * 16 + lg;
        size_t row1 = row0 + 8;
#pragma unroll
        for (int nf = 0; nf < 4; nf++) {
            int ncol = nblock + wn + nf * 8 + lt * 2;
            if (MODE == 1) {
                *(float2*)(Vout + row0 * 2048 + ncol) = make_float2(acc[mf][nf][0], acc[mf][nf][1]);
                *(float2*)(Vout + row1 * 2048 + ncol) = make_float2(acc[mf][nf][2], acc[mf][nf][3]);
            } else if (ncol < 2048) {
                int pair = (ncol & 127) >> 1;
                float c0 = fc[row0 * 64 + pair], s0 = fs[row0 * 64 + pair];
                float c1 = fc[row1 * 64 + pair], s1 = fs[row1 * 64 + pair];
                float q00 = (acc[mf][nf][0] * c0 - acc[mf][nf][1] * s0) * QSCALE_LOG2E;
                float q01 = (acc[mf][nf][0] * s0 + acc[mf][nf][1] * c0) * QSCALE_LOG2E;
                float q10 = (acc[mf][nf][2] * c1 - acc[mf][nf][3] * s1) * QSCALE_LOG2E;
                float q11 = (acc[mf][nf][2] * s1 + acc[mf][nf][3] * c1) * QSCALE_LOG2E;
                __half2 h0 = __floats2half2_rn(q00, q01);
                __half2 h1 = __floats2half2_rn(q10, q11);
                float2 f0 = __half22float2(h0), f1 = __half22float2(h1);
                *(__half2*)(qh + row0 * 2048 + ncol) = h0;
                *(__half2*)(qh + row1 * 2048 + ncol) = h1;
                *(__half2*)(ql + row0 * 2048 + ncol) = __floats2half2_rn(q00 - f0.x, q01 - f0.y);
                *(__half2*)(ql + row1 * 2048 + ncol) = __floats2half2_rn(q10 - f1.x, q11 - f1.y);
            } else if (ncol < 2560) {
                int kcol = ncol - 2048;
                int pair = (kcol & 127) >> 1;
                float c0 = fc[row0 * 64 + pair], s0 = fs[row0 * 64 + pair];
                float c1 = fc[row1 * 64 + pair], s1 = fs[row1 * 64 + pair];
                float k00 = acc[mf][nf][0] * c0 - acc[mf][nf][1] * s0;
                float k01 = acc[mf][nf][0] * s0 + acc[mf][nf][1] * c0;
                float k10 = acc[mf][nf][2] * c1 - acc[mf][nf][3] * s1;
                float k11 = acc[mf][nf][2] * s1 + acc[mf][nf][3] * c1;
                *(__half2*)(kh + row0 * 512 + kcol) = __floats2half2_rn(k00, k01);
                *(__half2*)(kh + row1 * 512 + kcol) = __floats2half2_rn(k10, k11);
            } else {
                int vcol = ncol - 2560;
                *(float2*)(Vout + row0 * 512 + vcol) = make_float2(acc[mf][nf][0], acc[mf][nf][1]);
                *(float2*)(Vout + row1 * 512 + vcol) = make_float2(acc[mf][nf][2], acc[mf][nf][3]);
            }
        }
    }
}

// ---------------- V transpose (hi only) ----------------
__global__ void __launch_bounds__(256) transpose_v(const float* __restrict__ V,
                                                   __half* __restrict__ vth)
{
    __shared__ float t[32][33];
    int kv = blockIdx.z, t0 = blockIdx.x * 32, d0 = blockIdx.y * 32;
    int cc = threadIdx.x & 31, rr = threadIdx.x >> 5;
#pragma unroll
    for (int i = 0; i < 4; i++) {
        int tok = rr + i * 8;
        t[tok][cc] = V[((size_t)(t0 + tok) * NKV + kv) * HD + d0 + cc];
    }
    __syncthreads();
#pragma unroll
    for (int i = 0; i < 4; i++) {
        int dd = rr + i * 8;
        size_t o = ((size_t)kv * HD + d0 + dd) * T_TOK + t0 + cc;
        vth[o] = __float2half_rn(t[cc][dd]);
    }
}

// ---------------- flash attention: 128-key tiles, two 64-halves per barrier ----------------
__global__ void __launch_bounds__(256) flash_hmma(
    const __half* __restrict__ qh, const __half* __restrict__ ql,
    const __half* __restrict__ kh, const __half* __restrict__ vth,
    const int* __restrict__ sid, __half* __restrict__ Aout)
{
    __half* S = (__half*)dyn_smem;
    const int tid = threadIdx.x, wid = tid >> 5, lane = tid & 31;
    const int lg = lane >> 2, lt = lane & 3;
    const int h = blockIdx.y, kv = h >> 2;
    const int q0 = (gridDim.x - 1 - blockIdx.x) * FQB;

#pragma unroll
    for (int i = 0; i < 16; i++) {
        int id = tid + i * 256;
        int sp = id >> 11, rem = id & 2047;
        int row = rem >> 4, ch = rem & 15;
        const __half* src = (sp ? ql : qh) + ((size_t)(q0 + row) * NH + h) * HD + ch * 8;
        cp16(S + sp * QL_H + row * KROW + ch * 8, src);
    }
    asm volatile("cp.async.commit_group;" ::: "memory");

#define F_ISSUE(KB, ST) do {                                                          \
    __half* _s = S + STG0_H + (ST) * STG_H;                                           \
    int _t0 = (KB) * FKB;                                                             \
    _Pragma("unroll")                                                                 \
    for (int _i = 0; _i < 8; _i++) {      /* K: 128 rows x 16 ch */                   \
        int _id = tid + _i * 256;                                                     \
        int _row = _id >> 4, _ch = _id & 15;                                          \
        cp16(_s + _row * KROW + _ch * 8,                                              \
             kh + ((size_t)(_t0 + _row) * NKV + kv) * HD + _ch * 8);                  \
    }                                                                                 \
    _Pragma("unroll")                                                                 \
    for (int _i = 0; _i < 8; _i++) {      /* V: 128 d-rows x 16 tok-ch */             \
        int _id = tid + _i * 256;                                                     \
        int _row = _id >> 4, _ch = _id & 15;                                          \
        cp16(_s + KT_H + _row * KROW + _ch * 8,                                       \
             vth + ((size_t)kv * HD + _row) * T_TOK + _t0 + _ch * 8);                 \
    }                                                                                 \
    asm volatile("cp.async.commit_group;" ::: "memory");                              \
} while (0)

    const int qi0 = q0 + wid * 16 + lg, qi1 = qi0 + 8;
    const int sqr0 = sid[qi0], sqr1 = sid[qi1];
    const int sq_first = sid[q0];
    const int sq_last  = sid[q0 + FQB - 1];
    const int kbe = q0 / FKB;              // inclusive; covers keys up to q0+127
    int kb0 = kbe;
    for (int kb = 0; kb <= kbe; kb++) {
        if (sid[kb * FKB + FKB - 1] >= sq_first) { kb0 = kb; break; }
    }

    F_ISSUE(kb0, 0);
    if (kb0 + 1 <= kbe) F_ISSUE(kb0 + 1, 1);

    float o[16][4];
#pragma unroll
    for (int i = 0; i < 16; i++)
#pragma unroll
        for (int j = 0; j < 4; j++) o[i][j] = 0.f;
    float m0 = -1.0e30f, l0 = 0.f, m1 = -1.0e30f, l1 = 0.f;

    const uint32_t Sb = smem_u32(S);
    const uint32_t q_off = Sb + (((wid * 16 + (lane & 15)) * KROW) + (lane >> 4) * 8) * 2;
    const int k_row = ((lane >> 4) & 1) * 8 + (lane & 7);
    const int k_ch  = ((lane >> 3) & 1) * 8;
    const int v_row = lane & 7;
    const int v_ch  = (lane >> 3) * 8;

    for (int kb = kb0; kb <= kbe; kb++) {
        int st = (kb - kb0) & 1;
        if (kb + 1 <= kbe) asm volatile("cp.async.wait_group 1;" ::: "memory");
        else               asm volatile("cp.async.wait_group 0;" ::: "memory");
        __syncthreads();

        const uint32_t Kb = Sb + (STG0_H + st * STG_H) * 2;
        const uint32_t Vb = Kb + KT_H * 2;

#pragma unroll
        for (int half64 = 0; half64 < 2; half64++) {
            const uint32_t Kbh = Kb + half64 * 64 * KROW * 2;

            // ---- S = (Qh + Ql) Kh^T ----
            float sf[8][4];
#pragma unroll
            for (int nf = 0; nf < 8; nf++)
#pragma unroll
                for (int q = 0; q < 4; q++) sf[nf][q] = 0.f;

#pragma unroll
            for (int ks = 0; ks < 8; ks++) {
                uint32_t ah[4], al[4];
                LDSM4(ah, q_off + ks * 32);
                LDSM4(al, q_off + ks * 32 + QL_H * 2);
#pragma unroll
                for (int np = 0; np < 4; np++) {
                    uint32_t bo = Kbh + ((np * 16 + k_row) * KROW + ks * 16 + k_ch) * 2;
                    uint32_t b4h[4];
                    LDSM4(b4h, bo);
#pragma unroll
                    for (int hh = 0; hh < 2; hh++) {
                        int nf = np * 2 + hh;
                        mma16816(sf[nf], ah, b4h + hh * 2);
                        mma16816(sf[nf], al, b4h + hh * 2);
                    }
                }
            }

            // ---- mask (skipped for fully-allowed interior half-tiles) ----
            const int kbase = kb * FKB + half64 * 64;
            bool full = (kbase + 64 <= q0) && (sid[kbase] == sq_last);
            if (!full) {
#pragma unroll
                for (int nf = 0; nf < 8; nf++) {
                    int c0 = kbase + nf * 8 + lt * 2;
                    int sk0 = sid[c0], sk1 = sid[c0 + 1];
                    if (c0 > qi0     || sk0 != sqr0) sf[nf][0] = -1.0e30f;
                    if (c0 + 1 > qi0 || sk1 != sqr0) sf[nf][1] = -1.0e30f;
                    if (c0 > qi1     || sk0 != sqr1) sf[nf][2] = -1.0e30f;
                    if (c0 + 1 > qi1 || sk1 != sqr1) sf[nf][3] = -1.0e30f;
                }
            }

            // ---- online softmax (base-2, fp16x2 exp) ----
            float mx0 = -1.0e30f, mx1 = -1.0e30f;
#pragma unroll
            for (int nf = 0; nf < 8; nf++) {
                mx0 = fmaxf(mx0, fmaxf(sf[nf][0], sf[nf][1]));
                mx1 = fmaxf(mx1, fmaxf(sf[nf][2], sf[nf][3]));
            }
            mx0 = fmaxf(mx0, __shfl_xor_sync(0xffffffffu, mx0, 1));
            mx0 = fmaxf(mx0, __shfl_xor_sync(0xffffffffu, mx0, 2));
            mx1 = fmaxf(mx1, __shfl_xor_sync(0xffffffffu, mx1, 1));
            mx1 = fmaxf(mx1, __shfl_xor_sync(0xffffffffu, mx1, 2));
            float mn0 = fmaxf(m0, mx0), mn1 = fmaxf(m1, mx1);
            float a0 = ex2_f32(m0 - mn0), a1 = ex2_f32(m1 - mn1);
            float sum0 = 0.f, sum1 = 0.f;
            uint32_t ph[4][4];
#pragma unroll
            for (int nf = 0; nf < 8; nf++) {
                uint32_t e01 = ex2_f16x2(__floats2half2_rn(sf[nf][0] - mn0, sf[nf][1] - mn0));
                uint32_t e23 = ex2_f16x2(__floats2half2_rn(sf[nf][2] - mn1, sf[nf][3] - mn1));
                float2 f01 = __half22float2(*(__half2*)&e01);
                float2 f23 = __half22float2(*(__half2*)&e23);
                sum0 += f01.x + f01.y;
                sum1 += f23.x + f23.y;
                int ksv = nf >> 1, up = (nf & 1) ? 2 : 0;
                ph[ksv][up + 0] = e01;
                ph[ksv][up + 1] = e23;
            }
            sum0 += __shfl_xor_sync(0xffffffffu, sum0, 1);
            sum0 += __shfl_xor_sync(0xffffffffu, sum0, 2);
            sum1 += __shfl_xor_sync(0xffffffffu, sum1, 1);
            sum1 += __shfl_xor_sync(0xffffffffu, sum1, 2);
            l0 = l0 * a0 + sum0; m0 = mn0;
            l1 = l1 * a1 + sum1; m1 = mn1;

            // ---- rescale O, then O += P Vh ----
#pragma unroll
            for (int nf2 = 0; nf2 < 16; nf2++) {
                o[nf2][0] *= a0; o[nf2][1] *= a0;
                o[nf2][2] *= a1; o[nf2][3] *= a1;
            }
#pragma unroll
            for (int nf2 = 0; nf2 < 16; nf2++) {
                uint32_t vo = Vb + ((nf2 * 8 + v_row) * KROW + half64 * 64 + v_ch) * 2;
                uint32_t vh[8];
                LDSM4(vh, vo);
                LDSM4(vh + 4, vo + 64);
#pragma unroll
                for (int ksv = 0; ksv < 4; ksv++)
                    mma16816(o[nf2], ph[ksv], vh + ksv * 2);
            }
        }

        __syncthreads();
        if (kb + 2 <= kbe) F_ISSUE(kb + 2, st);
    }

    // ---- epilogue: fp16 output ----
    float i0 = 1.0f / l0, i1 = 1.0f / l1;
    int r0 = q0 + wid * 16 + lg;
#pragma unroll
    for (int nf2 = 0; nf2 < 16; nf2++) {
        int col = nf2 * 8 + lt * 2;
        size_t b0 = ((size_t)r0 * NH + h) * HD + col;
        size_t b1 = ((size_t)(r0 + 8) * NH + h) * HD + col;
        *(__half2*)(Aout + b0) = __floats2half2_rn(o[nf2][0] * i0, o[nf2][1] * i0);
        *(__half2*)(Aout + b1) = __floats2half2_rn(o[nf2][2] * i1, o[nf2][3] * i1);
    }
}

// ----------------------------------------------------------------
extern "C" void kernel_launch(void* const* d_in, const int* in_sizes, int n_in,
                              void* d_out, int out_size)
{
    const float* x   = (const float*)d_in[0];
    const float* wq  = (const float*)d_in[1];
    const float* wk  = (const float*)d_in[2];
    const float* wv  = (const float*)d_in[3];
    const float* wo  = (const float*)d_in[4];
    const float* fc  = (const float*)d_in[5];
    const float* fs  = (const float*)d_in[6];
    const int*   sid = (const int*)d_in[7];
    float* out = (float*)d_out;

    float *Vp;
    __half *xh, *ah, *wqkvh, *wqkvl, *woh;
    __half *qhp, *qlp, *khp, *vthp;
    cudaGetSymbolAddress((void**)&Vp, g_V);
    cudaGetSymbolAddress((void**)&xh, g_xh);
    cudaGetSymbolAddress((void**)&ah, g_ah);
    cudaGetSymbolAddress((void**)&wqkvh, g_wqkvh);
    cudaGetSymbolAddress((void**)&wqkvl, g_wqkvl);
    cudaGetSymbolAddress((void**)&woh, g_woh);
    cudaGetSymbolAddress((void**)&qhp, g_qh);
    cudaGetSymbolAddress((void**)&qlp, g_ql);
    cudaGetSymbolAddress((void**)&khp, g_kh);
    cudaGetSymbolAddress((void**)&vthp, g_vth);

    cudaFuncSetAttribute((const void*)gemm_hmma<0,1>, cudaFuncAttributeMaxDynamicSharedMemorySize, GEMM_SMEM);
    cudaFuncSetAttribute((const void*)gemm_hmma<0,0>, cudaFuncAttributeMaxDynamicSharedMemorySize, GEMM_SMEM);
    cudaFuncSetAttribute((const void*)gemm_hmma<1,0>, cudaFuncAttributeMaxDynamicSharedMemorySize, GEMM_SMEM);
    cudaFuncSetAttribute((const void*)flash_hmma, cudaFuncAttributeMaxDynamicSharedMemorySize, FLASH_SMEM);

    pack_hi<<<(T_TOK * DIM / 4 + 255) / 256, 256>>>(x, xh, T_TOK * DIM / 4);
    pack_w_all<<<dim3(DIM / 32, 160), 256>>>(wq, wk, wv, wo, wqkvh, wqkvl, woh);

    // Q projection: 2-product, tiles 0..15
    gemm_hmma<0,1><<<dim3(16, T_TOK / BM), 256, GEMM_SMEM>>>(
        xh, wqkvh, wqkvl, qhp, qlp, khp, Vp, fc, fs, 0);
    // K/V projection: 1-product, tiles 16..23
    gemm_hmma<0,0><<<dim3(8, T_TOK / BM), 256, GEMM_SMEM>>>(
        xh, wqkvh, wqkvl, qhp, qlp, khp, Vp, fc, fs, 16);

    transpose_v<<<dim3(T_TOK / 32, HD / 32, NKV), 256>>>(Vp, vthp);
    flash_hmma<<<dim3(T_TOK / FQB, NH), 256, FLASH_SMEM>>>(
        qhp, qlp, khp, vthp, sid, ah);
    gemm_hmma<1,0><<<dim3(DIM / BN, T_TOK / BM), 256, GEMM_SMEM>>>(
        ah, woh, nullptr, nullptr, nullptr, nullptr, out, nullptr, nullptr, 0);
}

// round 16
// speedup vs baseline: 1.8723x; 1.1709x over previous
#include <cuda_runtime.h>
#include <cuda_fp16.h>
#include <cstdint>
#include <math.h>

// ---------------- problem constants ----------------
#define T_TOK   4096
#define DIM     2048
#define NH      16
#define NKV     4
#define HD      128
#define QSCALE_LOG2E 0.12751744f   // 1/sqrt(128) * log2(e), absorbed into Q

// ---------------- HMMA GEMM constants ----------------
#define BM 128
#define BN 128
#define BK 32
#define GPAD 40
#define GBH_OFF (128 * GPAD)
#define GSTG_H  (GBH_OFF + 2 * 128 * GPAD)
#define STAGE_B (GSTG_H * 2)
#define NSTAGE 3
#define GEMM_SMEM (NSTAGE * STAGE_B)

// ---------------- flash constants (FKB=128, processed as 2x64 halves) ----------------
#define FQB  128
#define FKB  128
#define KROW 136
#define QL_H   (FQB * KROW)
#define STG0_H (2 * QL_H)
#define KT_H   (FKB * KROW)
#define STG_H  (2 * KT_H)
#define FLASH_SMEM ((STG0_H + 2 * STG_H) * 2)

extern __shared__ __align__(16) char dyn_smem[];

// -------- scratch (device globals) --------
__device__ float  g_V[T_TOK * NKV * HD];
__device__ __half g_xh[T_TOK * DIM];
__device__ __half g_ah[T_TOK * DIM];
__device__ __half g_wqkvh[3072 * DIM];
__device__ __half g_woh[DIM * DIM];
__device__ __half g_qh[T_TOK * NH * HD],  g_ql[T_TOK * NH * HD];
__device__ __half g_kh[T_TOK * NKV * HD];
__device__ __half g_vth[NKV * HD * T_TOK];

// ---------------- helpers ----------------
__device__ __forceinline__ uint32_t smem_u32(const void* p) {
    uint32_t a;
    asm("{ .reg .u64 t; cvta.to.shared.u64 t, %1; cvt.u32.u64 %0, t; }" : "=r"(a) : "l"(p));
    return a;
}
__device__ __forceinline__ void cp16(void* dst, const void* src) {
    uint32_t d;
    asm("{ .reg .u64 t; cvta.to.shared.u64 t, %1; cvt.u32.u64 %0, t; }" : "=r"(d) : "l"(dst));
    asm volatile("cp.async.cg.shared.global [%0], [%1], 16;" :: "r"(d), "l"(src));
}
__device__ __forceinline__ void mma16816(float* c, const uint32_t* a, const uint32_t* b) {
    asm volatile(
        "mma.sync.aligned.m16n8k16.row.col.f32.f16.f16.f32 "
        "{%0,%1,%2,%3}, {%4,%5,%6,%7}, {%8,%9}, {%0,%1,%2,%3};"
        : "+f"(c[0]), "+f"(c[1]), "+f"(c[2]), "+f"(c[3])
        : "r"(a[0]), "r"(a[1]), "r"(a[2]), "r"(a[3]), "r"(b[0]), "r"(b[1]));
}
#define LDSM4(R, a) \
    asm volatile("ldmatrix.sync.aligned.m8n8.x4.shared.b16 {%0,%1,%2,%3}, [%4];" \
        : "=r"((R)[0]), "=r"((R)[1]), "=r"((R)[2]), "=r"((R)[3]) : "r"(a))
__device__ __forceinline__ uint32_t ex2_f16x2(__half2 x) {
    uint32_t r;
    asm("ex2.approx.f16x2 %0, %1;" : "=r"(r) : "r"(*(uint32_t*)&x));
    return r;
}
__device__ __forceinline__ float ex2_f32(float x) {
    float r;
    asm("ex2.approx.f32 %0, %1;" : "=f"(r) : "f"(x));
    return r;
}

// ---------------- pack x: fp32 -> hi fp16 ----------------
__global__ void __launch_bounds__(256) pack_hi(const float* __restrict__ in,
                                               __half* __restrict__ oh, int n4) {
    int i = blockIdx.x * blockDim.x + threadIdx.x;
    if (i >= n4) return;
    float4 v = ((const float4*)in)[i];
    ((__half2*)oh)[i * 2 + 0] = __floats2half2_rn(v.x, v.y);
    ((__half2*)oh)[i * 2 + 1] = __floats2half2_rn(v.z, v.w);
}

// ---------------- fused weight transpose (hi only now) ----------------
__global__ void __launch_bounds__(256) pack_w_all(const float* __restrict__ wq,
                                                  const float* __restrict__ wk,
                                                  const float* __restrict__ wv,
                                                  const float* __restrict__ wo,
                                                  __half* __restrict__ qkvh,
                                                  __half* __restrict__ woh) {
    __shared__ float t[32][33];
    int k0 = blockIdx.x * 32;
    int by = blockIdx.y;
    const float* w; __half* oh;
    int Nsrc, nbase, n0;
    if (by < 64)       { w = wq; Nsrc = 2048; nbase = 0;    n0 = by * 32;        oh = qkvh; }
    else if (by < 80)  { w = wk; Nsrc = 512;  nbase = 2048; n0 = (by - 64) * 32; oh = qkvh; }
    else if (by < 96)  { w = wv; Nsrc = 512;  nbase = 2560; n0 = (by - 80) * 32; oh = qkvh; }
    else               { w = wo; Nsrc = 2048; nbase = 0;    n0 = (by - 96) * 32; oh = woh;  }
    int tid = threadIdx.x;
    int cc = tid & 31, rr = tid >> 5;
#pragma unroll
    for (int i = 0; i < 4; i++) {
        int row = rr + i * 8;
        t[row][cc] = w[(size_t)(k0 + row) * Nsrc + n0 + cc];
    }
    __syncthreads();
#pragma unroll
    for (int i = 0; i < 4; i++) {
        int n = rr + i * 8;
        size_t o = (size_t)(nbase + n0 + n) * DIM + k0 + cc;
        oh[o] = __float2half_rn(t[cc][n]);
    }
}

// ---------------- HMMA GEMM (1-product only now) ----------------
// MODE 0: QKV epilogue (RoPE on Q cols + Q hi/lo split, RoPE on K, V fp32)
// MODE 1: plain fp32 output
template<int MODE>
__global__ void __launch_bounds__(256, 2) gemm_hmma(const __half* __restrict__ Ah,
                                                    const __half* __restrict__ Bh,
                                                    __half* __restrict__ qh,
                                                    __half* __restrict__ ql,
                                                    __half* __restrict__ kh,
                                                    float* __restrict__ Vout,
                                                    const float* __restrict__ fc,
                                                    const float* __restrict__ fs) {
    __half* sm = (__half*)dyn_smem;
    const int tid = threadIdx.x;
    const int wid = tid >> 5, lane = tid & 31;
    const int wm = (wid & 1) * 64, wn = (wid >> 1) * 32;
    const int lg = lane >> 2, lt = lane & 3;

    const int ntile = blockIdx.x;
    const size_t arow0 = (size_t)blockIdx.y * BM;
    const size_t brow0 = (size_t)ntile * BN;

    float acc[4][4][4];
#pragma unroll
    for (int mf = 0; mf < 4; mf++)
#pragma unroll
        for (int nf = 0; nf < 4; nf++)
#pragma unroll
            for (int q = 0; q < 4; q++) acc[mf][nf][q] = 0.f;

    const int NKT = DIM / BK;

#define G_ISSUE(KT, ST) do {                                                     \
    __half* _sb = sm + (ST) * GSTG_H;                                            \
    int _k0 = (KT) * BK;                                                         \
    _Pragma("unroll")                                                            \
    for (int _i = 0; _i < 4; _i++) {                                             \
        int _idx = tid + _i * 256;                                               \
        if (_idx < 512) {                                                        \
            int _row = _idx >> 2, _ch = _idx & 3;                                \
            cp16(_sb + _row * GPAD + _ch * 8,                                    \
                 Ah + (arow0 + _row) * DIM + _k0 + _ch * 8);                     \
        } else {                                                                 \
            int _j = _idx - 512;                                                 \
            int _row = _j >> 2, _ch = _j & 3;                                    \
            cp16(_sb + GBH_OFF + _row * GPAD + _ch * 8,                          \
                 Bh + (brow0 + _row) * DIM + _k0 + _ch * 8);                     \
        }                                                                        \
    }                                                                            \
    asm volatile("cp.async.commit_group;" ::: "memory");                         \
} while (0)

    G_ISSUE(0, 0);
    G_ISSUE(1, 1);

    const uint32_t smb = smem_u32(sm);
    const int a_row = (lane & 15);
    const int a_ch  = (lane >> 4) * 8;
    const int b_row = ((lane >> 4) & 1) * 8 + (lane & 7);
    const int b_ch  = ((lane >> 3) & 1) * 8;

    for (int kt = 0; kt < NKT; kt++) {
        int st = kt % NSTAGE;
        if (kt + 1 < NKT) asm volatile("cp.async.wait_group 1;" ::: "memory");
        else              asm volatile("cp.async.wait_group 0;" ::: "memory");
        __syncthreads();
        if (kt + 2 < NKT) G_ISSUE(kt + 2, (kt + 2) % NSTAGE);

        const uint32_t sb = smb + st * STAGE_B;

#pragma unroll
        for (int ks = 0; ks < 2; ks++) {
            uint32_t ah[4][4];
#pragma unroll
            for (int mf = 0; mf < 4; mf++) {
                uint32_t ao = sb + ((wm + mf * 16 + a_row) * GPAD + ks * 16 + a_ch) * 2;
                LDSM4(ah[mf], ao);
            }
#pragma unroll
            for (int np = 0; np < 2; np++) {
                uint32_t bo = sb + (GBH_OFF + (wn + np * 16 + b_row) * GPAD + ks * 16 + b_ch) * 2;
                uint32_t b4h[4];
                LDSM4(b4h, bo);
#pragma unroll
                for (int half = 0; half < 2; half++) {
                    int nf = np * 2 + half;
#pragma unroll
                    for (int mf = 0; mf < 4; mf++)
                        mma16816(acc[mf][nf], ah[mf], b4h + half * 2);
                }
            }
        }
    }

    // ---- epilogue ----
    const int nblock = ntile * BN;
#pragma unroll
    for (int mf = 0; mf < 4; mf++) {
        size_t row0 = arow0 + wm + mf * 16 + lg;
        size_t row1 = row0 + 8;
#pragma unroll
        for (int nf = 0; nf < 4; nf++) {
            int ncol = nblock + wn + nf * 8 + lt * 2;
            if (MODE == 1) {
                *(float2*)(Vout + row0 * 2048 + ncol) = make_float2(acc[mf][nf][0], acc[mf][nf][1]);
                *(float2*)(Vout + row1 * 2048 + ncol) = make_float2(acc[mf][nf][2], acc[mf][nf][3]);
            } else if (ncol < 2048) {
                int pair = (ncol & 127) >> 1;
                float c0 = fc[row0 * 64 + pair], s0 = fs[row0 * 64 + pair];
                float c1 = fc[row1 * 64 + pair], s1 = fs[row1 * 64 + pair];
                float q00 = (acc[mf][nf][0] * c0 - acc[mf][nf][1] * s0) * QSCALE_LOG2E;
                float q01 = (acc[mf][nf][0] * s0 + acc[mf][nf][1] * c0) * QSCALE_LOG2E;
                float q10 = (acc[mf][nf][2] * c1 - acc[mf][nf][3] * s1) * QSCALE_LOG2E;
                float q11 = (acc[mf][nf][2] * s1 + acc[mf][nf][3] * c1) * QSCALE_LOG2E;
                __half2 h0 = __floats2half2_rn(q00, q01);
                __half2 h1 = __floats2half2_rn(q10, q11);
                float2 f0 = __half22float2(h0), f1 = __half22float2(h1);
                *(__half2*)(qh + row0 * 2048 + ncol) = h0;
                *(__half2*)(qh + row1 * 2048 + ncol) = h1;
                *(__half2*)(ql + row0 * 2048 + ncol) = __floats2half2_rn(q00 - f0.x, q01 - f0.y);
                *(__half2*)(ql + row1 * 2048 + ncol) = __floats2half2_rn(q10 - f1.x, q11 - f1.y);
            } else if (ncol < 2560) {
                int kcol = ncol - 2048;
                int pair = (kcol & 127) >> 1;
                float c0 = fc[row0 * 64 + pair], s0 = fs[row0 * 64 + pair];
                float c1 = fc[row1 * 64 + pair], s1 = fs[row1 * 64 + pair];
                float k00 = acc[mf][nf][0] * c0 - acc[mf][nf][1] * s0;
                float k01 = acc[mf][nf][0] * s0 + acc[mf][nf][1] * c0;
                float k10 = acc[mf][nf][2] * c1 - acc[mf][nf][3] * s1;
                float k11 = acc[mf][nf][2] * s1 + acc[mf][nf][3] * c1;
                *(__half2*)(kh + row0 * 512 + kcol) = __floats2half2_rn(k00, k01);
                *(__half2*)(kh + row1 * 512 + kcol) = __floats2half2_rn(k10, k11);
            } else {
                int vcol = ncol - 2560;
                *(float2*)(Vout + row0 * 512 + vcol) = make_float2(acc[mf][nf][0], acc[mf][nf][1]);
                *(float2*)(Vout + row1 * 512 + vcol) = make_float2(acc[mf][nf][2], acc[mf][nf][3]);
            }
        }
    }
}

// ---------------- V transpose (hi only) ----------------
__global__ void __launch_bounds__(256) transpose_v(const float* __restrict__ V,
                                                   __half* __restrict__ vth)
{
    __shared__ float t[32][33];
    int kv = blockIdx.z, t0 = blockIdx.x * 32, d0 = blockIdx.y * 32;
    int cc = threadIdx.x & 31, rr = threadIdx.x >> 5;
#pragma unroll
    for (int i = 0; i < 4; i++) {
        int tok = rr + i * 8;
        t[tok][cc] = V[((size_t)(t0 + tok) * NKV + kv) * HD + d0 + cc];
    }
    __syncthreads();
#pragma unroll
    for (int i = 0; i < 4; i++) {
        int dd = rr + i * 8;
        size_t o = ((size_t)kv * HD + d0 + dd) * T_TOK + t0 + cc;
        vth[o] = __float2half_rn(t[cc][dd]);
    }
}

// ---------------- flash attention (unchanged from R15) ----------------
__global__ void __launch_bounds__(256) flash_hmma(
    const __half* __restrict__ qh, const __half* __restrict__ ql,
    const __half* __restrict__ kh, const __half* __restrict__ vth,
    const int* __restrict__ sid, __half* __restrict__ Aout)
{
    __half* S = (__half*)dyn_smem;
    const int tid = threadIdx.x, wid = tid >> 5, lane = tid & 31;
    const int lg = lane >> 2, lt = lane & 3;
    const int h = blockIdx.y, kv = h >> 2;
    const int q0 = (gridDim.x - 1 - blockIdx.x) * FQB;

#pragma unroll
    for (int i = 0; i < 16; i++) {
        int id = tid + i * 256;
        int sp = id >> 11, rem = id & 2047;
        int row = rem >> 4, ch = rem & 15;
        const __half* src = (sp ? ql : qh) + ((size_t)(q0 + row) * NH + h) * HD + ch * 8;
        cp16(S + sp * QL_H + row * KROW + ch * 8, src);
    }
    asm volatile("cp.async.commit_group;" ::: "memory");

#define F_ISSUE(KB, ST) do {                                                          \
    __half* _s = S + STG0_H + (ST) * STG_H;                                           \
    int _t0 = (KB) * FKB;                                                             \
    _Pragma("unroll")                                                                 \
    for (int _i = 0; _i < 8; _i++) {                                                  \
        int _id = tid + _i * 256;                                                     \
        int _row = _id >> 4, _ch = _id & 15;                                          \
        cp16(_s + _row * KROW + _ch * 8,                                              \
             kh + ((size_t)(_t0 + _row) * NKV + kv) * HD + _ch * 8);                  \
    }                                                                                 \
    _Pragma("unroll")                                                                 \
    for (int _i = 0; _i < 8; _i++) {                                                  \
        int _id = tid + _i * 256;                                                     \
        int _row = _id >> 4, _ch = _id & 15;                                          \
        cp16(_s + KT_H + _row * KROW + _ch * 8,                                       \
             vth + ((size_t)kv * HD + _row) * T_TOK + _t0 + _ch * 8);                 \
    }                                                                                 \
    asm volatile("cp.async.commit_group;" ::: "memory");                              \
} while (0)

    const int qi0 = q0 + wid * 16 + lg, qi1 = qi0 + 8;
    const int sqr0 = sid[qi0], sqr1 = sid[qi1];
    const int sq_first = sid[q0];
    const int sq_last  = sid[q0 + FQB - 1];
    const int kbe = q0 / FKB;
    int kb0 = kbe;
    for (int kb = 0; kb <= kbe; kb++) {
        if (sid[kb * FKB + FKB - 1] >= sq_first) { kb0 = kb; break; }
    }

    F_ISSUE(kb0, 0);
    if (kb0 + 1 <= kbe) F_ISSUE(kb0 + 1, 1);

    float o[16][4];
#pragma unroll
    for (int i = 0; i < 16; i++)
#pragma unroll
        for (int j = 0; j < 4; j++) o[i][j] = 0.f;
    float m0 = -1.0e30f, l0 = 0.f, m1 = -1.0e30f, l1 = 0.f;

    const uint32_t Sb = smem_u32(S);
    const uint32_t q_off = Sb + (((wid * 16 + (lane & 15)) * KROW) + (lane >> 4) * 8) * 2;
    const int k_row = ((lane >> 4) & 1) * 8 + (lane & 7);
    const int k_ch  = ((lane >> 3) & 1) * 8;
    const int v_row = lane & 7;
    const int v_ch  = (lane >> 3) * 8;

    for (int kb = kb0; kb <= kbe; kb++) {
        int st = (kb - kb0) & 1;
        if (kb + 1 <= kbe) asm volatile("cp.async.wait_group 1;" ::: "memory");
        else               asm volatile("cp.async.wait_group 0;" ::: "memory");
        __syncthreads();

        const uint32_t Kb = Sb + (STG0_H + st * STG_H) * 2;
        const uint32_t Vb = Kb + KT_H * 2;

#pragma unroll
        for (int half64 = 0; half64 < 2; half64++) {
            const uint32_t Kbh = Kb + half64 * 64 * KROW * 2;

            float sf[8][4];
#pragma unroll
            for (int nf = 0; nf < 8; nf++)
#pragma unroll
                for (int q = 0; q < 4; q++) sf[nf][q] = 0.f;

#pragma unroll
            for (int ks = 0; ks < 8; ks++) {
                uint32_t ah[4], al[4];
                LDSM4(ah, q_off + ks * 32);
                LDSM4(al, q_off + ks * 32 + QL_H * 2);
#pragma unroll
                for (int np = 0; np < 4; np++) {
                    uint32_t bo = Kbh + ((np * 16 + k_row) * KROW + ks * 16 + k_ch) * 2;
                    uint32_t b4h[4];
                    LDSM4(b4h, bo);
#pragma unroll
                    for (int hh = 0; hh < 2; hh++) {
                        int nf = np * 2 + hh;
                        mma16816(sf[nf], ah, b4h + hh * 2);
                        mma16816(sf[nf], al, b4h + hh * 2);
                    }
                }
            }

            const int kbase = kb * FKB + half64 * 64;
            bool full = (kbase + 64 <= q0) && (sid[kbase] == sq_last);
            if (!full) {
#pragma unroll
                for (int nf = 0; nf < 8; nf++) {
                    int c0 = kbase + nf * 8 + lt * 2;
                    int sk0 = sid[c0], sk1 = sid[c0 + 1];
                    if (c0 > qi0     || sk0 != sqr0) sf[nf][0] = -1.0e30f;
                    if (c0 + 1 > qi0 || sk1 != sqr0) sf[nf][1] = -1.0e30f;
                    if (c0 > qi1     || sk0 != sqr1) sf[nf][2] = -1.0e30f;
                    if (c0 + 1 > qi1 || sk1 != sqr1) sf[nf][3] = -1.0e30f;
                }
            }

            float mx0 = -1.0e30f, mx1 = -1.0e30f;
#pragma unroll
            for (int nf = 0; nf < 8; nf++) {
                mx0 = fmaxf(mx0, fmaxf(sf[nf][0], sf[nf][1]));
                mx1 = fmaxf(mx1, fmaxf(sf[nf][2], sf[nf][3]));
            }
            mx0 = fmaxf(mx0, __shfl_xor_sync(0xffffffffu, mx0, 1));
            mx0 = fmaxf(mx0, __shfl_xor_sync(0xffffffffu, mx0, 2));
            mx1 = fmaxf(mx1, __shfl_xor_sync(0xffffffffu, mx1, 1));
            mx1 = fmaxf(mx1, __shfl_xor_sync(0xffffffffu, mx1, 2));
            float mn0 = fmaxf(m0, mx0), mn1 = fmaxf(m1, mx1);
            float a0 = ex2_f32(m0 - mn0), a1 = ex2_f32(m1 - mn1);
            float sum0 = 0.f, sum1 = 0.f;
            uint32_t ph[4][4];
#pragma unroll
            for (int nf = 0; nf < 8; nf++) {
                uint32_t e01 = ex2_f16x2(__floats2half2_rn(sf[nf][0] - mn0, sf[nf][1] - mn0));
                uint32_t e23 = ex2_f16x2(__floats2half2_rn(sf[nf][2] - mn1, sf[nf][3] - mn1));
                float2 f01 = __half22float2(*(__half2*)&e01);
                float2 f23 = __half22float2(*(__half2*)&e23);
                sum0 += f01.x + f01.y;
                sum1 += f23.x + f23.y;
                int ksv = nf >> 1, up = (nf & 1) ? 2 : 0;
                ph[ksv][up + 0] = e01;
                ph[ksv][up + 1] = e23;
            }
            sum0 += __shfl_xor_sync(0xffffffffu, sum0, 1);
            sum0 += __shfl_xor_sync(0xffffffffu, sum0, 2);
            sum1 += __shfl_xor_sync(0xffffffffu, sum1, 1);
            sum1 += __shfl_xor_sync(0xffffffffu, sum1, 2);
            l0 = l0 * a0 + sum0; m0 = mn0;
            l1 = l1 * a1 + sum1; m1 = mn1;

#pragma unroll
            for (int nf2 = 0; nf2 < 16; nf2++) {
                o[nf2][0] *= a0; o[nf2][1] *= a0;
                o[nf2][2] *= a1; o[nf2][3] *= a1;
            }
#pragma unroll
            for (int nf2 = 0; nf2 < 16; nf2++) {
                uint32_t vo = Vb + ((nf2 * 8 + v_row) * KROW + half64 * 64 + v_ch) * 2;
                uint32_t vh[8];
                LDSM4(vh, vo);
                LDSM4(vh + 4, vo + 64);
#pragma unroll
                for (int ksv = 0; ksv < 4; ksv++)
                    mma16816(o[nf2], ph[ksv], vh + ksv * 2);
            }
        }

        __syncthreads();
        if (kb + 2 <= kbe) F_ISSUE(kb + 2, st);
    }

    float i0 = 1.0f / l0, i1 = 1.0f / l1;
    int r0 = q0 + wid * 16 + lg;
#pragma unroll
    for (int nf2 = 0; nf2 < 16; nf2++) {
        int col = nf2 * 8 + lt * 2;
        size_t b0 = ((size_t)r0 * NH + h) * HD + col;
        size_t b1 = ((size_t)(r0 + 8) * NH + h) * HD + col;
        *(__half2*)(Aout + b0) = __floats2half2_rn(o[nf2][0] * i0, o[nf2][1] * i0);
        *(__half2*)(Aout + b1) = __floats2half2_rn(o[nf2][2] * i1, o[nf2][3] * i1);
    }
}

// ----------------------------------------------------------------
extern "C" void kernel_launch(void* const* d_in, const int* in_sizes, int n_in,
                              void* d_out, int out_size)
{
    const float* x   = (const float*)d_in[0];
    const float* wq  = (const float*)d_in[1];
    const float* wk  = (const float*)d_in[2];
    const float* wv  = (const float*)d_in[3];
    const float* wo  = (const float*)d_in[4];
    const float* fc  = (const float*)d_in[5];
    const float* fs  = (const float*)d_in[6];
    const int*   sid = (const int*)d_in[7];
    float* out = (float*)d_out;

    float *Vp;
    __half *xh, *ah, *wqkvh, *woh;
    __half *qhp, *qlp, *khp, *vthp;
    cudaGetSymbolAddress((void**)&Vp, g_V);
    cudaGetSymbolAddress((void**)&xh, g_xh);
    cudaGetSymbolAddress((void**)&ah, g_ah);
    cudaGetSymbolAddress((void**)&wqkvh, g_wqkvh);
    cudaGetSymbolAddress((void**)&woh, g_woh);
    cudaGetSymbolAddress((void**)&qhp, g_qh);
    cudaGetSymbolAddress((void**)&qlp, g_ql);
    cudaGetSymbolAddress((void**)&khp, g_kh);
    cudaGetSymbolAddress((void**)&vthp, g_vth);

    cudaFuncSetAttribute((const void*)gemm_hmma<0>, cudaFuncAttributeMaxDynamicSharedMemorySize, GEMM_SMEM);
    cudaFuncSetAttribute((const void*)gemm_hmma<1>, cudaFuncAttributeMaxDynamicSharedMemorySize, GEMM_SMEM);
    cudaFuncSetAttribute((const void*)flash_hmma, cudaFuncAttributeMaxDynamicSharedMemorySize, FLASH_SMEM);

    pack_hi<<<(T_TOK * DIM / 4 + 255) / 256, 256>>>(x, xh, T_TOK * DIM / 4);
    pack_w_all<<<dim3(DIM / 32, 160), 256>>>(wq, wk, wv, wo, wqkvh, woh);

    // QKV projection: single launch, 1-product, all 24 column tiles
    gemm_hmma<0><<<dim3(24, T_TOK / BM), 256, GEMM_SMEM>>>(
        xh, wqkvh, qhp, qlp, khp, Vp, fc, fs);

    transpose_v<<<dim3(T_TOK / 32, HD / 32, NKV), 256>>>(Vp, vthp);
    flash_hmma<<<dim3(T_TOK / FQB, NH), 256, FLASH_SMEM>>>(
        qhp, qlp, khp, vthp, sid, ah);
    gemm_hmma<1><<<dim3(DIM / BN, T_TOK / BM), 256, GEMM_SMEM>>>(
        ah, woh, nullptr, nullptr, nullptr, out, nullptr, nullptr);
}

// round 17
// speedup vs baseline: 2.0395x; 1.0893x over previous
#include <cuda_runtime.h>
#include <cuda_fp16.h>
#include <cstdint>
#include <math.h>

// ---------------- problem constants ----------------
#define T_TOK   4096
#define DIM     2048
#define NH      16
#define NKV     4
#define HD      128
#define QSCALE_LOG2E 0.12751744f   // 1/sqrt(128) * log2(e), absorbed into Q

// ---------------- HMMA GEMM constants (1-product, 4-stage) ----------------
#define BM 128
#define BN 128
#define BK 32
#define GPAD 40
#define GBH_OFF (128 * GPAD)
#define GSTG_H  (2 * 128 * GPAD)       // 10240 halves/stage (A + B)
#define STAGE_B (GSTG_H * 2)           // 20480 B
#define NSTAGE 4
#define GEMM_SMEM (NSTAGE * STAGE_B)   // 81920 B (x2 CTAs = 164 KB)

// ---------------- flash constants (FKB=128, 2x64 halves; Q hi only) ----------------
#define FQB  128
#define FKB  128
#define KROW 136
#define QL_H   (FQB * KROW)            // 17408 (Q hi)
#define KT_H   (FKB * KROW)            // 17408
#define STG_H  (2 * KT_H)              // 34816 (K + V)
#define FLASH_SMEM ((QL_H + 2 * STG_H) * 2)   // 174080 B

extern __shared__ __align__(16) char dyn_smem[];

// -------- scratch (device globals) --------
__device__ float  g_V[T_TOK * NKV * HD];
__device__ __half g_xh[T_TOK * DIM];
__device__ __half g_ah[T_TOK * DIM];
__device__ __half g_wqkvh[3072 * DIM];
__device__ __half g_woh[DIM * DIM];
__device__ __half g_qh[T_TOK * NH * HD];
__device__ __half g_kh[T_TOK * NKV * HD];
__device__ __half g_vth[NKV * HD * T_TOK];

// ---------------- helpers ----------------
__device__ __forceinline__ uint32_t smem_u32(const void* p) {
    uint32_t a;
    asm("{ .reg .u64 t; cvta.to.shared.u64 t, %1; cvt.u32.u64 %0, t; }" : "=r"(a) : "l"(p));
    return a;
}
__device__ __forceinline__ void cp16(void* dst, const void* src) {
    uint32_t d;
    asm("{ .reg .u64 t; cvta.to.shared.u64 t, %1; cvt.u32.u64 %0, t; }" : "=r"(d) : "l"(dst));
    asm volatile("cp.async.cg.shared.global [%0], [%1], 16;" :: "r"(d), "l"(src));
}
__device__ __forceinline__ void mma16816(float* c, const uint32_t* a, const uint32_t* b) {
    asm volatile(
        "mma.sync.aligned.m16n8k16.row.col.f32.f16.f16.f32 "
        "{%0,%1,%2,%3}, {%4,%5,%6,%7}, {%8,%9}, {%0,%1,%2,%3};"
        : "+f"(c[0]), "+f"(c[1]), "+f"(c[2]), "+f"(c[3])
        : "r"(a[0]), "r"(a[1]), "r"(a[2]), "r"(a[3]), "r"(b[0]), "r"(b[1]));
}
#define LDSM4(R, a) \
    asm volatile("ldmatrix.sync.aligned.m8n8.x4.shared.b16 {%0,%1,%2,%3}, [%4];" \
        : "=r"((R)[0]), "=r"((R)[1]), "=r"((R)[2]), "=r"((R)[3]) : "r"(a))
__device__ __forceinline__ uint32_t ex2_f16x2(__half2 x) {
    uint32_t r;
    asm("ex2.approx.f16x2 %0, %1;" : "=r"(r) : "r"(*(uint32_t*)&x));
    return r;
}
__device__ __forceinline__ float ex2_f32(float x) {
    float r;
    asm("ex2.approx.f32 %0, %1;" : "=f"(r) : "f"(x));
    return r;
}

// ---------------- pack x: fp32 -> hi fp16 ----------------
__global__ void __launch_bounds__(256) pack_hi(const float* __restrict__ in,
                                               __half* __restrict__ oh, int n4) {
    int i = blockIdx.x * blockDim.x + threadIdx.x;
    if (i >= n4) return;
    float4 v = ((const float4*)in)[i];
    ((__half2*)oh)[i * 2 + 0] = __floats2half2_rn(v.x, v.y);
    ((__half2*)oh)[i * 2 + 1] = __floats2half2_rn(v.z, v.w);
}

// ---------------- fused weight transpose (hi only) ----------------
__global__ void __launch_bounds__(256) pack_w_all(const float* __restrict__ wq,
                                                  const float* __restrict__ wk,
                                                  const float* __restrict__ wv,
                                                  const float* __restrict__ wo,
                                                  __half* __restrict__ qkvh,
                                                  __half* __restrict__ woh) {
    __shared__ float t[32][33];
    int k0 = blockIdx.x * 32;
    int by = blockIdx.y;
    const float* w; __half* oh;
    int Nsrc, nbase, n0;
    if (by < 64)       { w = wq; Nsrc = 2048; nbase = 0;    n0 = by * 32;        oh = qkvh; }
    else if (by < 80)  { w = wk; Nsrc = 512;  nbase = 2048; n0 = (by - 64) * 32; oh = qkvh; }
    else if (by < 96)  { w = wv; Nsrc = 512;  nbase = 2560; n0 = (by - 80) * 32; oh = qkvh; }
    else               { w = wo; Nsrc = 2048; nbase = 0;    n0 = (by - 96) * 32; oh = woh;  }
    int tid = threadIdx.x;
    int cc = tid & 31, rr = tid >> 5;
#pragma unroll
    for (int i = 0; i < 4; i++) {
        int row = rr + i * 8;
        t[row][cc] = w[(size_t)(k0 + row) * Nsrc + n0 + cc];
    }
    __syncthreads();
#pragma unroll
    for (int i = 0; i < 4; i++) {
        int n = rr + i * 8;
        size_t o = (size_t)(nbase + n0 + n) * DIM + k0 + cc;
        oh[o] = __float2half_rn(t[cc][n]);
    }
}

// ---------------- HMMA GEMM (1-product, 4-stage) ----------------
// MODE 0: QKV epilogue (RoPE Q/K -> fp16, V fp32); MODE 1: plain fp32 output.
template<int MODE>
__global__ void __launch_bounds__(256, 2) gemm_hmma(const __half* __restrict__ Ah,
                                                    const __half* __restrict__ Bh,
                                                    __half* __restrict__ qh,
                                                    __half* __restrict__ kh,
                                                    float* __restrict__ Vout,
                                                    const float* __restrict__ fc,
                                                    const float* __restrict__ fs) {
    __half* sm = (__half*)dyn_smem;
    const int tid = threadIdx.x;
    const int wid = tid >> 5, lane = tid & 31;
    const int wm = (wid & 1) * 64, wn = (wid >> 1) * 32;
    const int lg = lane >> 2, lt = lane & 3;

    const int ntile = blockIdx.x;
    const size_t arow0 = (size_t)blockIdx.y * BM;
    const size_t brow0 = (size_t)ntile * BN;

    float acc[4][4][4];
#pragma unroll
    for (int mf = 0; mf < 4; mf++)
#pragma unroll
        for (int nf = 0; nf < 4; nf++)
#pragma unroll
            for (int q = 0; q < 4; q++) acc[mf][nf][q] = 0.f;

    const int NKT = DIM / BK;

#define G_ISSUE(KT, ST) do {                                                     \
    __half* _sb = sm + (ST) * GSTG_H;                                            \
    int _k0 = (KT) * BK;                                                         \
    _Pragma("unroll")                                                            \
    for (int _i = 0; _i < 4; _i++) {                                             \
        int _idx = tid + _i * 256;                                               \
        if (_idx < 512) {                                                        \
            int _row = _idx >> 2, _ch = _idx & 3;                                \
            cp16(_sb + _row * GPAD + _ch * 8,                                    \
                 Ah + (arow0 + _row) * DIM + _k0 + _ch * 8);                     \
        } else {                                                                 \
            int _j = _idx - 512;                                                 \
            int _row = _j >> 2, _ch = _j & 3;                                    \
            cp16(_sb + GBH_OFF + _row * GPAD + _ch * 8,                          \
                 Bh + (brow0 + _row) * DIM + _k0 + _ch * 8);                     \
        }                                                                        \
    }                                                                            \
    asm volatile("cp.async.commit_group;" ::: "memory");                         \
} while (0)

    G_ISSUE(0, 0);
    G_ISSUE(1, 1);
    G_ISSUE(2, 2);

    const uint32_t smb = smem_u32(sm);
    const int a_row = (lane & 15);
    const int a_ch  = (lane >> 4) * 8;
    const int b_row = ((lane >> 4) & 1) * 8 + (lane & 7);
    const int b_ch  = ((lane >> 3) & 1) * 8;

    for (int kt = 0; kt < NKT; kt++) {
        int st = kt % NSTAGE;
        if (kt + 1 < NKT) asm volatile("cp.async.wait_group 2;" ::: "memory");
        else              asm volatile("cp.async.wait_group 0;" ::: "memory");
        __syncthreads();
        if (kt + 3 < NKT) G_ISSUE(kt + 3, (kt + 3) % NSTAGE);

        const uint32_t sb = smb + st * STAGE_B;

#pragma unroll
        for (int ks = 0; ks < 2; ks++) {
            uint32_t ah[4][4];
#pragma unroll
            for (int mf = 0; mf < 4; mf++) {
                uint32_t ao = sb + ((wm + mf * 16 + a_row) * GPAD + ks * 16 + a_ch) * 2;
                LDSM4(ah[mf], ao);
            }
#pragma unroll
            for (int np = 0; np < 2; np++) {
                uint32_t bo = sb + (GBH_OFF + (wn + np * 16 + b_row) * GPAD + ks * 16 + b_ch) * 2;
                uint32_t b4h[4];
                LDSM4(b4h, bo);
#pragma unroll
                for (int half = 0; half < 2; half++) {
                    int nf = np * 2 + half;
#pragma unroll
                    for (int mf = 0; mf < 4; mf++)
                        mma16816(acc[mf][nf], ah[mf], b4h + half * 2);
                }
            }
        }
    }

    // ---- epilogue ----
    const int nblock = ntile * BN;
#pragma unroll
    for (int mf = 0; mf < 4; mf++) {
        size_t row0 = arow0 + wm + mf * 16 + lg;
        size_t row1 = row0 + 8;
#pragma unroll
        for (int nf = 0; nf < 4; nf++) {
            int ncol = nblock + wn + nf * 8 + lt * 2;
            if (MODE == 1) {
                *(float2*)(Vout + row0 * 2048 + ncol) = make_float2(acc[mf][nf][0], acc[mf][nf][1]);
                *(float2*)(Vout + row1 * 2048 + ncol) = make_float2(acc[mf][nf][2], acc[mf][nf][3]);
            } else if (ncol < 2048) {
                int pair = (ncol & 127) >> 1;
                float c0 = fc[row0 * 64 + pair], s0 = fs[row0 * 64 + pair];
                float c1 = fc[row1 * 64 + pair], s1 = fs[row1 * 64 + pair];
                float q00 = (acc[mf][nf][0] * c0 - acc[mf][nf][1] * s0) * QSCALE_LOG2E;
                float q01 = (acc[mf][nf][0] * s0 + acc[mf][nf][1] * c0) * QSCALE_LOG2E;
                float q10 = (acc[mf][nf][2] * c1 - acc[mf][nf][3] * s1) * QSCALE_LOG2E;
                float q11 = (acc[mf][nf][2] * s1 + acc[mf][nf][3] * c1) * QSCALE_LOG2E;
                *(__half2*)(qh + row0 * 2048 + ncol) = __floats2half2_rn(q00, q01);
                *(__half2*)(qh + row1 * 2048 + ncol) = __floats2half2_rn(q10, q11);
            } else if (ncol < 2560) {
                int kcol = ncol - 2048;
                int pair = (kcol & 127) >> 1;
                float c0 = fc[row0 * 64 + pair], s0 = fs[row0 * 64 + pair];
                float c1 = fc[row1 * 64 + pair], s1 = fs[row1 * 64 + pair];
                float k00 = acc[mf][nf][0] * c0 - acc[mf][nf][1] * s0;
                float k01 = acc[mf][nf][0] * s0 + acc[mf][nf][1] * c0;
                float k10 = acc[mf][nf][2] * c1 - acc[mf][nf][3] * s1;
                float k11 = acc[mf][nf][2] * s1 + acc[mf][nf][3] * c1;
                *(__half2*)(kh + row0 * 512 + kcol) = __floats2half2_rn(k00, k01);
                *(__half2*)(kh + row1 * 512 + kcol) = __floats2half2_rn(k10, k11);
            } else {
                int vcol = ncol - 2560;
                *(float2*)(Vout + row0 * 512 + vcol) = make_float2(acc[mf][nf][0], acc[mf][nf][1]);
                *(float2*)(Vout + row1 * 512 + vcol) = make_float2(acc[mf][nf][2], acc[mf][nf][3]);
            }
        }
    }
}

// ---------------- V transpose (hi only) ----------------
__global__ void __launch_bounds__(256) transpose_v(const float* __restrict__ V,
                                                   __half* __restrict__ vth)
{
    __shared__ float t[32][33];
    int kv = blockIdx.z, t0 = blockIdx.x * 32, d0 = blockIdx.y * 32;
    int cc = threadIdx.x & 31, rr = threadIdx.x >> 5;
#pragma unroll
    for (int i = 0; i < 4; i++) {
        int tok = rr + i * 8;
        t[tok][cc] = V[((size_t)(t0 + tok) * NKV + kv) * HD + d0 + cc];
    }
    __syncthreads();
#pragma unroll
    for (int i = 0; i < 4; i++) {
        int dd = rr + i * 8;
        size_t o = ((size_t)kv * HD + d0 + dd) * T_TOK + t0 + cc;
        vth[o] = __float2half_rn(t[cc][dd]);
    }
}

// ---------------- flash attention: 1-product QK (Qh*Kh), 128-key tiles ----------------
__global__ void __launch_bounds__(256) flash_hmma(
    const __half* __restrict__ qh,
    const __half* __restrict__ kh, const __half* __restrict__ vth,
    const int* __restrict__ sid, __half* __restrict__ Aout)
{
    __half* S = (__half*)dyn_smem;
    const int tid = threadIdx.x, wid = tid >> 5, lane = tid & 31;
    const int lg = lane >> 2, lt = lane & 3;
    const int h = blockIdx.y, kv = h >> 2;
    const int q0 = (gridDim.x - 1 - blockIdx.x) * FQB;

    // Q tile (hi only): 128 rows x 16 chunks
#pragma unroll
    for (int i = 0; i < 8; i++) {
        int id = tid + i * 256;
        int row = id >> 4, ch = id & 15;
        cp16(S + row * KROW + ch * 8,
             qh + ((size_t)(q0 + row) * NH + h) * HD + ch * 8);
    }
    asm volatile("cp.async.commit_group;" ::: "memory");

#define F_ISSUE(KB, ST) do {                                                          \
    __half* _s = S + QL_H + (ST) * STG_H;                                             \
    int _t0 = (KB) * FKB;                                                             \
    _Pragma("unroll")                                                                 \
    for (int _i = 0; _i < 8; _i++) {                                                  \
        int _id = tid + _i * 256;                                                     \
        int _row = _id >> 4, _ch = _id & 15;                                          \
        cp16(_s + _row * KROW + _ch * 8,                                              \
             kh + ((size_t)(_t0 + _row) * NKV + kv) * HD + _ch * 8);                  \
    }                                                                                 \
    _Pragma("unroll")                                                                 \
    for (int _i = 0; _i < 8; _i++) {                                                  \
        int _id = tid + _i * 256;                                                     \
        int _row = _id >> 4, _ch = _id & 15;                                          \
        cp16(_s + KT_H + _row * KROW + _ch * 8,                                       \
             vth + ((size_t)kv * HD + _row) * T_TOK + _t0 + _ch * 8);                 \
    }                                                                                 \
    asm volatile("cp.async.commit_group;" ::: "memory");                              \
} while (0)

    const int qi0 = q0 + wid * 16 + lg, qi1 = qi0 + 8;
    const int sqr0 = sid[qi0], sqr1 = sid[qi1];
    const int sq_first = sid[q0];
    const int sq_last  = sid[q0 + FQB - 1];
    const int kbe = q0 / FKB;
    int kb0 = kbe;
    for (int kb = 0; kb <= kbe; kb++) {
        if (sid[kb * FKB + FKB - 1] >= sq_first) { kb0 = kb; break; }
    }

    F_ISSUE(kb0, 0);
    if (kb0 + 1 <= kbe) F_ISSUE(kb0 + 1, 1);

    float o[16][4];
#pragma unroll
    for (int i = 0; i < 16; i++)
#pragma unroll
        for (int j = 0; j < 4; j++) o[i][j] = 0.f;
    float m0 = -1.0e30f, l0 = 0.f, m1 = -1.0e30f, l1 = 0.f;

    const uint32_t Sb = smem_u32(S);
    const uint32_t q_off = Sb + (((wid * 16 + (lane & 15)) * KROW) + (lane >> 4) * 8) * 2;
    const int k_row = ((lane >> 4) & 1) * 8 + (lane & 7);
    const int k_ch  = ((lane >> 3) & 1) * 8;
    const int v_row = lane & 7;
    const int v_ch  = (lane >> 3) * 8;

    for (int kb = kb0; kb <= kbe; kb++) {
        int st = (kb - kb0) & 1;
        if (kb + 1 <= kbe) asm volatile("cp.async.wait_group 1;" ::: "memory");
        else               asm volatile("cp.async.wait_group 0;" ::: "memory");
        __syncthreads();

        const uint32_t Kb = Sb + (QL_H + st * STG_H) * 2;
        const uint32_t Vb = Kb + KT_H * 2;

#pragma unroll
        for (int half64 = 0; half64 < 2; half64++) {
            const uint32_t Kbh = Kb + half64 * 64 * KROW * 2;

            float sf[8][4];
#pragma unroll
            for (int nf = 0; nf < 8; nf++)
#pragma unroll
                for (int q = 0; q < 4; q++) sf[nf][q] = 0.f;

#pragma unroll
            for (int ks = 0; ks < 8; ks++) {
                uint32_t ah[4];
                LDSM4(ah, q_off + ks * 32);
#pragma unroll
                for (int np = 0; np < 4; np++) {
                    uint32_t bo = Kbh + ((np * 16 + k_row) * KROW + ks * 16 + k_ch) * 2;
                    uint32_t b4h[4];
                    LDSM4(b4h, bo);
#pragma unroll
                    for (int hh = 0; hh < 2; hh++)
                        mma16816(sf[np * 2 + hh], ah, b4h + hh * 2);
                }
            }

            const int kbase = kb * FKB + half64 * 64;
            bool full = (kbase + 64 <= q0) && (sid[kbase] == sq_last);
            if (!full) {
#pragma unroll
                for (int nf = 0; nf < 8; nf++) {
                    int c0 = kbase + nf * 8 + lt * 2;
                    int sk0 = sid[c0], sk1 = sid[c0 + 1];
                    if (c0 > qi0     || sk0 != sqr0) sf[nf][0] = -1.0e30f;
                    if (c0 + 1 > qi0 || sk1 != sqr0) sf[nf][1] = -1.0e30f;
                    if (c0 > qi1     || sk0 != sqr1) sf[nf][2] = -1.0e30f;
                    if (c0 + 1 > qi1 || sk1 != sqr1) sf[nf][3] = -1.0e30f;
                }
            }

            float mx0 = -1.0e30f, mx1 = -1.0e30f;
#pragma unroll
            for (int nf = 0; nf < 8; nf++) {
                mx0 = fmaxf(mx0, fmaxf(sf[nf][0], sf[nf][1]));
                mx1 = fmaxf(mx1, fmaxf(sf[nf][2], sf[nf][3]));
            }
            mx0 = fmaxf(mx0, __shfl_xor_sync(0xffffffffu, mx0, 1));
            mx0 = fmaxf(mx0, __shfl_xor_sync(0xffffffffu, mx0, 2));
            mx1 = fmaxf(mx1, __shfl_xor_sync(0xffffffffu, mx1, 1));
            mx1 = fmaxf(mx1, __shfl_xor_sync(0xffffffffu, mx1, 2));
            float mn0 = fmaxf(m0, mx0), mn1 = fmaxf(m1, mx1);
            float a0 = ex2_f32(m0 - mn0), a1 = ex2_f32(m1 - mn1);
            float sum0 = 0.f, sum1 = 0.f;
            uint32_t ph[4][4];
#pragma unroll
            for (int nf = 0; nf < 8; nf++) {
                uint32_t e01 = ex2_f16x2(__floats2half2_rn(sf[nf][0] - mn0, sf[nf][1] - mn0));
                uint32_t e23 = ex2_f16x2(__floats2half2_rn(sf[nf][2] - mn1, sf[nf][3] - mn1));
                float2 f01 = __half22float2(*(__half2*)&e01);
                float2 f23 = __half22float2(*(__half2*)&e23);
                sum0 += f01.x + f01.y;
                sum1 += f23.x + f23.y;
                int ksv = nf >> 1, up = (nf & 1) ? 2 : 0;
                ph[ksv][up + 0] = e01;
                ph[ksv][up + 1] = e23;
            }
            sum0 += __shfl_xor_sync(0xffffffffu, sum0, 1);
            sum0 += __shfl_xor_sync(0xffffffffu, sum0, 2);
            sum1 += __shfl_xor_sync(0xffffffffu, sum1, 1);
            sum1 += __shfl_xor_sync(0xffffffffu, sum1, 2);
            l0 = l0 * a0 + sum0; m0 = mn0;
            l1 = l1 * a1 + sum1; m1 = mn1;

#pragma unroll
            for (int nf2 = 0; nf2 < 16; nf2++) {
                o[nf2][0] *= a0; o[nf2][1] *= a0;
                o[nf2][2] *= a1; o[nf2][3] *= a1;
            }
#pragma unroll
            for (int nf2 = 0; nf2 < 16; nf2++) {
                uint32_t vo = Vb + ((nf2 * 8 + v_row) * KROW + half64 * 64 + v_ch) * 2;
                uint32_t vh[8];
                LDSM4(vh, vo);
                LDSM4(vh + 4, vo + 64);
#pragma unroll
                for (int ksv = 0; ksv < 4; ksv++)
                    mma16816(o[nf2], ph[ksv], vh + ksv * 2);
            }
        }

        __syncthreads();
        if (kb + 2 <= kbe) F_ISSUE(kb + 2, st);
    }

    float i0 = 1.0f / l0, i1 = 1.0f / l1;
    int r0 = q0 + wid * 16 + lg;
#pragma unroll
    for (int nf2 = 0; nf2 < 16; nf2++) {
        int col = nf2 * 8 + lt * 2;
        size_t b0 = ((size_t)r0 * NH + h) * HD + col;
        size_t b1 = ((size_t)(r0 + 8) * NH + h) * HD + col;
        *(__half2*)(Aout + b0) = __floats2half2_rn(o[nf2][0] * i0, o[nf2][1] * i0);
        *(__half2*)(Aout + b1) = __floats2half2_rn(o[nf2][2] * i1, o[nf2][3] * i1);
    }
}

// ----------------------------------------------------------------
extern "C" void kernel_launch(void* const* d_in, const int* in_sizes, int n_in,
                              void* d_out, int out_size)
{
    const float* x   = (const float*)d_in[0];
    const float* wq  = (const float*)d_in[1];
    const float* wk  = (const float*)d_in[2];
    const float* wv  = (const float*)d_in[3];
    const float* wo  = (const float*)d_in[4];
    const float* fc  = (const float*)d_in[5];
    const float* fs  = (const float*)d_in[6];
    const int*   sid = (const int*)d_in[7];
    float* out = (float*)d_out;

    float *Vp;
    __half *xh, *ah, *wqkvh, *woh;
    __half *qhp, *khp, *vthp;
    cudaGetSymbolAddress((void**)&Vp, g_V);
    cudaGetSymbolAddress((void**)&xh, g_xh);
    cudaGetSymbolAddress((void**)&ah, g_ah);
    cudaGetSymbolAddress((void**)&wqkvh, g_wqkvh);
    cudaGetSymbolAddress((void**)&woh, g_woh);
    cudaGetSymbolAddress((void**)&qhp, g_qh);
    cudaGetSymbolAddress((void**)&khp, g_kh);
    cudaGetSymbolAddress((void**)&vthp, g_vth);

    cudaFuncSetAttribute((const void*)gemm_hmma<0>, cudaFuncAttributeMaxDynamicSharedMemorySize, GEMM_SMEM);
    cudaFuncSetAttribute((const void*)gemm_hmma<1>, cudaFuncAttributeMaxDynamicSharedMemorySize, GEMM_SMEM);
    cudaFuncSetAttribute((const void*)flash_hmma, cudaFuncAttributeMaxDynamicSharedMemorySize, FLASH_SMEM);

    pack_hi<<<(T_TOK * DIM / 4 + 255) / 256, 256>>>(x, xh, T_TOK * DIM / 4);
    pack_w_all<<<dim3(DIM / 32, 160), 256>>>(wq, wk, wv, wo, wqkvh, woh);

    gemm_hmma<0><<<dim3(24, T_TOK / BM), 256, GEMM_SMEM>>>(
        xh, wqkvh, qhp, khp, Vp, fc, fs);

    transpose_v<<<dim3(T_TOK / 32, HD / 32, NKV), 256>>>(Vp, vthp);
    flash_hmma<<<dim3(T_TOK / FQB, NH), 256, FLASH_SMEM>>>(
        qhp, khp, vthp, sid, ah);
    gemm_hmma<1><<<dim3(DIM / BN, T_TOK / BM), 256, GEMM_SMEM>>>(
        ah, woh, nullptr, nullptr, out, nullptr, nullptr);
}